// round 1
// baseline (speedup 1.0000x reference)
#include <cuda_runtime.h>
#include <math.h>
#include <stdint.h>

// ---------------- problem constants ----------------
#define NN      100000      // N_NODES
#define NE      800000      // N_EDGES
#define DD      64          // D
#define RM      8           // R_MOL
#define NM      5000        // N_MOL
#define NRE     40000       // N_RXN_EDGES
#define RR      4           // R_RXN
#define NB      1024        // N_RXN (batch)
#define DH      512         // DIM_HIDDEN
#define DO      703         // DIM_OUT

// ---------------- scratch (static device globals; no runtime alloc) ----------------
__device__ float g_hW [(size_t)RM * NN * DD];   // 204.8 MB, reused for reaction layer
__device__ float g_h1 [(size_t)NN * DD];        // layer1 agg/output
__device__ float g_h2 [(size_t)NN * DD];        // layer2 agg/output
__device__ float g_atts[(size_t)RM * NN];
__device__ float g_attd[(size_t)RM * NN];
__device__ float g_scores[NE];
__device__ float g_ex    [NE];
__device__ float g_max [NN];
__device__ float g_sum [NN];
__device__ float g_mol [(size_t)NM * DD];
__device__ float g_molr[(size_t)NM * DD];
__device__ float g_feat[(size_t)NB * 2 * DD];
__device__ float g_hid [(size_t)NB * DH];

// ---------------- small helpers ----------------
__device__ __forceinline__ void atomicMaxFloat(float* addr, float val) {
    if (val >= 0.f) atomicMax((int*)addr, __float_as_int(val));
    else            atomicMin((unsigned int*)addr, __float_as_uint(val));
}

__device__ __forceinline__ void red_add_v4(float* p, float4 v) {
    asm volatile("red.global.add.v4.f32 [%0], {%1,%2,%3,%4};"
                 :: "l"(p), "f"(v.x), "f"(v.y), "f"(v.z), "f"(v.w) : "memory");
}

__global__ void fill_kernel(float* __restrict__ p, float v, int n) {
    int i = blockIdx.x * blockDim.x + threadIdx.x;
    if (i < n) p[i] = v;
}

// ---------------- hW GEMM + fused attention logits ----------------
// hW[r][n][:] = h[n] @ W[r];  att_s[r*N+n] = hW.a_src[r]; att_d likewise.
// block: 256 threads = 32 nodes x 8 col-groups of 8; grid: (ceil(N/32), R)
__global__ void hw_att_kernel(const float* __restrict__ h,
                              const float* __restrict__ W,
                              const float* __restrict__ a_src,
                              const float* __restrict__ a_dst,
                              float* __restrict__ hW,
                              float* __restrict__ att_s,
                              float* __restrict__ att_d,
                              int N)
{
    const int r   = blockIdx.y;
    const int n0  = blockIdx.x * 32;
    const int tid = threadIdx.x;

    __shared__ float Ws[64 * 64];
    __shared__ float hs[32][65];

    const float* Wr = W + (size_t)r * 64 * 64;
    #pragma unroll
    for (int i = 0; i < 16; i++) Ws[tid + i * 256] = Wr[tid + i * 256];
    #pragma unroll
    for (int i = 0; i < 8; i++) {
        int idx = tid + i * 256;            // 0..2047
        int row = idx >> 6, col = idx & 63;
        int n = n0 + row;
        hs[row][col] = (n < N) ? h[(size_t)n * 64 + col] : 0.f;
    }
    __syncthreads();

    const int node = tid >> 3;
    const int cg   = (tid & 7) * 8;

    float acc[8];
    #pragma unroll
    for (int j = 0; j < 8; j++) acc[j] = 0.f;

    #pragma unroll 8
    for (int k = 0; k < 64; k++) {
        float hv  = hs[node][k];
        float4 w0 = *(const float4*)&Ws[k * 64 + cg];
        float4 w1 = *(const float4*)&Ws[k * 64 + cg + 4];
        acc[0] += hv * w0.x; acc[1] += hv * w0.y; acc[2] += hv * w0.z; acc[3] += hv * w0.w;
        acc[4] += hv * w1.x; acc[5] += hv * w1.y; acc[6] += hv * w1.z; acc[7] += hv * w1.w;
    }

    // fused attention partials (all lanes participate in shfl; guard stores only)
    float ps = 0.f, pd = 0.f;
    #pragma unroll
    for (int j = 0; j < 8; j++) {
        ps += acc[j] * a_src[r * 64 + cg + j];
        pd += acc[j] * a_dst[r * 64 + cg + j];
    }
    #pragma unroll
    for (int o = 4; o >= 1; o >>= 1) {
        ps += __shfl_xor_sync(0xffffffffu, ps, o);
        pd += __shfl_xor_sync(0xffffffffu, pd, o);
    }

    int n = n0 + node;
    if (n < N) {
        float* o = hW + ((size_t)r * N + n) * 64 + cg;
        *(float4*)(o)     = make_float4(acc[0], acc[1], acc[2], acc[3]);
        *(float4*)(o + 4) = make_float4(acc[4], acc[5], acc[6], acc[7]);
        if ((tid & 7) == 0) {
            att_s[(size_t)r * N + n] = ps;
            att_d[(size_t)r * N + n] = pd;
        }
    }
}

// ---------------- edge passes ----------------
__global__ void edge_scores_kernel(const int* __restrict__ src, const int* __restrict__ dst,
                                   const int* __restrict__ rel,
                                   const float* __restrict__ att_s, const float* __restrict__ att_d,
                                   float* __restrict__ scores, float* __restrict__ dmax,
                                   int E, int N)
{
    int e = blockIdx.x * blockDim.x + threadIdx.x;
    if (e >= E) return;
    int s = src[e], d = dst[e], r = rel[e];
    float v = att_s[(size_t)r * N + s] + att_d[(size_t)r * N + d];
    v = (v > 0.f) ? v : 0.2f * v;            // leaky_relu
    scores[e] = v;
    atomicMaxFloat(&dmax[d], v);
}

__global__ void edge_exp_kernel(const int* __restrict__ dst,
                                const float* __restrict__ scores, const float* __restrict__ dmax,
                                float* __restrict__ ex, float* __restrict__ dsum, int E)
{
    int e = blockIdx.x * blockDim.x + threadIdx.x;
    if (e >= E) return;
    int d = dst[e];
    float v = expf(scores[e] - dmax[d]);
    ex[e] = v;
    atomicAdd(&dsum[d], v);
}

// 16 threads per edge, float4 vector reductions
__global__ void edge_scatter_kernel(const int* __restrict__ src, const int* __restrict__ dst,
                                    const int* __restrict__ rel,
                                    const float* __restrict__ ex, const float* __restrict__ dsum,
                                    const float* __restrict__ hW,
                                    float* __restrict__ agg, int E, int N)
{
    int t = blockIdx.x * blockDim.x + threadIdx.x;
    int e = t >> 4;
    if (e >= E) return;
    int g = (t & 15) * 4;
    int s = src[e], d = dst[e], r = rel[e];
    float alpha = ex[e] / (dsum[d] + 1e-9f);
    float4 hv = *(const float4*)&hW[((size_t)r * N + s) * 64 + g];
    red_add_v4(&agg[(size_t)d * 64 + g],
               make_float4(alpha * hv.x, alpha * hv.y, alpha * hv.z, alpha * hv.w));
}

__global__ void elu_kernel(float* __restrict__ x, int n) {
    int i = blockIdx.x * blockDim.x + threadIdx.x;
    if (i >= n) return;
    float v = x[i];
    x[i] = (v > 0.f) ? v : expm1f(v);
}

// segment sum of [n,64] rows into out[seg[i]*ostride + ooff + :64]; 16 threads/row
__global__ void segsum_kernel(const float* __restrict__ x, const int* __restrict__ seg,
                              float* __restrict__ out, int n, int ostride, int ooff)
{
    int t = blockIdx.x * blockDim.x + threadIdx.x;
    int i = t >> 4;
    if (i >= n) return;
    int g = (t & 15) * 4;
    int s = seg[i];
    float4 v = *(const float4*)&x[(size_t)i * 64 + g];
    red_add_v4(&out[(size_t)s * ostride + ooff + g], v);
}

// ---------------- MLP head ----------------
// fc1: [NB,128] @ [128,512] + b -> PReLU.  16 rows per block, 512 threads (one col each).
__global__ void fc1_kernel(const float* __restrict__ feat, const float* __restrict__ w,
                           const float* __restrict__ b, const float* __restrict__ prelu,
                           float* __restrict__ out)
{
    const int r0 = blockIdx.x * 16;
    __shared__ float fs[16][128];
    for (int i = threadIdx.x; i < 16 * 128; i += blockDim.x)
        fs[i >> 7][i & 127] = feat[(size_t)(r0 + (i >> 7)) * 128 + (i & 127)];
    __syncthreads();

    const int col = threadIdx.x;   // 0..511
    float acc[16];
    #pragma unroll
    for (int j = 0; j < 16; j++) acc[j] = 0.f;
    for (int k = 0; k < 128; k++) {
        float wv = w[k * 512 + col];
        #pragma unroll
        for (int j = 0; j < 16; j++) acc[j] += fs[j][k] * wv;
    }
    float bb = b[col], p = prelu[0];
    #pragma unroll
    for (int j = 0; j < 16; j++) {
        float v = acc[j] + bb;
        out[(size_t)(r0 + j) * 512 + col] = (v > 0.f) ? v : p * v;
    }
}

// fc2: [NB,512] @ [512,703] + b. 16 rows per block, 704 threads (703 used).
__global__ void fc2_kernel(const float* __restrict__ hid, const float* __restrict__ w,
                           const float* __restrict__ b, float* __restrict__ out)
{
    const int r0 = blockIdx.x * 16;
    __shared__ float hs[16][512];
    for (int i = threadIdx.x; i < 16 * 512; i += blockDim.x)
        hs[i >> 9][i & 511] = hid[(size_t)(r0 + (i >> 9)) * 512 + (i & 511)];
    __syncthreads();

    const int col = threadIdx.x;
    if (col >= 703) return;
    float acc[16];
    #pragma unroll
    for (int j = 0; j < 16; j++) acc[j] = 0.f;
    for (int k = 0; k < 512; k++) {
        float wv = w[k * 703 + col];
        #pragma unroll
        for (int j = 0; j < 16; j++) acc[j] += hs[j][k] * wv;
    }
    float bb = b[col];
    #pragma unroll
    for (int j = 0; j < 16; j++)
        out[(size_t)(r0 + j) * 703 + col] = acc[j] + bb;
}

// ---------------- launch ----------------
static inline int cdiv(int a, int b) { return (a + b - 1) / b; }

extern "C" void kernel_launch(void* const* d_in, const int* in_sizes, int n_in,
                              void* d_out, int out_size)
{
    const float* node_feats = (const float*)d_in[0];
    const int*   edge_src   = (const int*)  d_in[1];
    const int*   edge_dst   = (const int*)  d_in[2];
    const int*   edge_rel   = (const int*)  d_in[3];
    const int*   node2mol   = (const int*)  d_in[4];
    const int*   rxn_src    = (const int*)  d_in[5];
    const int*   rxn_dst    = (const int*)  d_in[6];
    const int*   rxn_rel    = (const int*)  d_in[7];
    const int*   mol2rxn    = (const int*)  d_in[8];
    const float* W1    = (const float*)d_in[9];
    const float* as1   = (const float*)d_in[10];
    const float* ad1   = (const float*)d_in[11];
    const float* W2    = (const float*)d_in[12];
    const float* as2   = (const float*)d_in[13];
    const float* ad2   = (const float*)d_in[14];
    const float* Wr    = (const float*)d_in[15];
    const float* asr   = (const float*)d_in[16];
    const float* adr   = (const float*)d_in[17];
    const float* w_fc1 = (const float*)d_in[18];
    const float* b_fc1 = (const float*)d_in[19];
    const float* prelu = (const float*)d_in[20];
    const float* w_fc2 = (const float*)d_in[21];
    const float* b_fc2 = (const float*)d_in[22];
    float* out = (float*)d_out;

    float *p_hW, *p_h1, *p_h2, *p_atts, *p_attd, *p_scores, *p_ex,
          *p_max, *p_sum, *p_mol, *p_molr, *p_feat, *p_hid;
    cudaGetSymbolAddress((void**)&p_hW,    g_hW);
    cudaGetSymbolAddress((void**)&p_h1,    g_h1);
    cudaGetSymbolAddress((void**)&p_h2,    g_h2);
    cudaGetSymbolAddress((void**)&p_atts,  g_atts);
    cudaGetSymbolAddress((void**)&p_attd,  g_attd);
    cudaGetSymbolAddress((void**)&p_scores,g_scores);
    cudaGetSymbolAddress((void**)&p_ex,    g_ex);
    cudaGetSymbolAddress((void**)&p_max,   g_max);
    cudaGetSymbolAddress((void**)&p_sum,   g_sum);
    cudaGetSymbolAddress((void**)&p_mol,   g_mol);
    cudaGetSymbolAddress((void**)&p_molr,  g_molr);
    cudaGetSymbolAddress((void**)&p_feat,  g_feat);
    cudaGetSymbolAddress((void**)&p_hid,   g_hid);

    const float NEG_INF = -INFINITY;
    const int TB = 256;

    // ===== atom layer 1 =====
    fill_kernel<<<cdiv(NN, TB), TB>>>(p_max, NEG_INF, NN);
    fill_kernel<<<cdiv(NN, TB), TB>>>(p_sum, 0.f, NN);
    fill_kernel<<<cdiv(NN * DD, TB), TB>>>(p_h1, 0.f, NN * DD);
    hw_att_kernel<<<dim3(cdiv(NN, 32), RM), 256>>>(node_feats, W1, as1, ad1,
                                                   p_hW, p_atts, p_attd, NN);
    edge_scores_kernel<<<cdiv(NE, TB), TB>>>(edge_src, edge_dst, edge_rel,
                                             p_atts, p_attd, p_scores, p_max, NE, NN);
    edge_exp_kernel<<<cdiv(NE, TB), TB>>>(edge_dst, p_scores, p_max, p_ex, p_sum, NE);
    edge_scatter_kernel<<<cdiv(NE * 16, TB), TB>>>(edge_src, edge_dst, edge_rel,
                                                   p_ex, p_sum, p_hW, p_h1, NE, NN);
    elu_kernel<<<cdiv(NN * DD, TB), TB>>>(p_h1, NN * DD);

    // ===== atom layer 2 =====
    fill_kernel<<<cdiv(NN, TB), TB>>>(p_max, NEG_INF, NN);
    fill_kernel<<<cdiv(NN, TB), TB>>>(p_sum, 0.f, NN);
    fill_kernel<<<cdiv(NN * DD, TB), TB>>>(p_h2, 0.f, NN * DD);
    hw_att_kernel<<<dim3(cdiv(NN, 32), RM), 256>>>(p_h1, W2, as2, ad2,
                                                   p_hW, p_atts, p_attd, NN);
    edge_scores_kernel<<<cdiv(NE, TB), TB>>>(edge_src, edge_dst, edge_rel,
                                             p_atts, p_attd, p_scores, p_max, NE, NN);
    edge_exp_kernel<<<cdiv(NE, TB), TB>>>(edge_dst, p_scores, p_max, p_ex, p_sum, NE);
    edge_scatter_kernel<<<cdiv(NE * 16, TB), TB>>>(edge_src, edge_dst, edge_rel,
                                                   p_ex, p_sum, p_hW, p_h2, NE, NN);
    elu_kernel<<<cdiv(NN * DD, TB), TB>>>(p_h2, NN * DD);

    // ===== molecule readout =====
    fill_kernel<<<cdiv(NM * DD, TB), TB>>>(p_mol, 0.f, NM * DD);
    segsum_kernel<<<cdiv(NN * 16, TB), TB>>>(p_h2, node2mol, p_mol, NN, 64, 0);

    // ===== reaction-level RGAT =====
    fill_kernel<<<cdiv(NM, TB), TB>>>(p_max, NEG_INF, NM);
    fill_kernel<<<cdiv(NM, TB), TB>>>(p_sum, 0.f, NM);
    fill_kernel<<<cdiv(NM * DD, TB), TB>>>(p_molr, 0.f, NM * DD);
    hw_att_kernel<<<dim3(cdiv(NM, 32), RR), 256>>>(p_mol, Wr, asr, adr,
                                                   p_hW, p_atts, p_attd, NM);
    edge_scores_kernel<<<cdiv(NRE, TB), TB>>>(rxn_src, rxn_dst, rxn_rel,
                                              p_atts, p_attd, p_scores, p_max, NRE, NM);
    edge_exp_kernel<<<cdiv(NRE, TB), TB>>>(rxn_dst, p_scores, p_max, p_ex, p_sum, NRE);
    edge_scatter_kernel<<<cdiv(NRE * 16, TB), TB>>>(rxn_src, rxn_dst, rxn_rel,
                                                    p_ex, p_sum, p_hW, p_molr, NRE, NM);
    elu_kernel<<<cdiv(NM * DD, TB), TB>>>(p_molr, NM * DD);

    // ===== reaction readout: feat = [segsum(molr) | segsum(mol)] =====
    fill_kernel<<<cdiv(NB * 2 * DD, TB), TB>>>(p_feat, 0.f, NB * 2 * DD);
    segsum_kernel<<<cdiv(NM * 16, TB), TB>>>(p_molr, mol2rxn, p_feat, NM, 128, 0);
    segsum_kernel<<<cdiv(NM * 16, TB), TB>>>(p_mol,  mol2rxn, p_feat, NM, 128, 64);

    // ===== MLP head =====
    fc1_kernel<<<NB / 16, 512>>>(p_feat, w_fc1, b_fc1, prelu, p_hid);
    fc2_kernel<<<NB / 16, 704>>>(p_hid, w_fc2, b_fc2, out);
}

// round 2
// speedup vs baseline: 2.3834x; 2.3834x over previous
#include <cuda_runtime.h>
#include <math.h>
#include <stdint.h>

// ---------------- problem constants ----------------
#define NN      100000      // N_NODES
#define NE      800000      // N_EDGES
#define DD      64          // D
#define RM      8           // R_MOL
#define NM      5000        // N_MOL
#define NRE     40000       // N_RXN_EDGES
#define RR      4           // R_RXN
#define NB      1024        // N_RXN (batch)
#define DH      512         // DIM_HIDDEN
#define DO      703         // DIM_OUT

// ---------------- scratch (static device globals; no runtime alloc) ----------------
__device__ float g_hW [(size_t)RM * NN * DD];   // 204.8 MB, reused for reaction layer
__device__ float g_h1 [(size_t)NN * DD];
__device__ float g_h2 [(size_t)NN * DD];
__device__ float g_atts[(size_t)RM * NN];
__device__ float g_attd[(size_t)RM * NN];
__device__ float g_scores[NE];
__device__ float g_ex    [NE];
__device__ float g_max [NN];
__device__ float g_sum [NN];
__device__ float g_mol [(size_t)NM * DD];
__device__ float g_molr[(size_t)NM * DD];
__device__ float g_feat[(size_t)NB * 2 * DD];
__device__ float g_hid [(size_t)NB * DH];

// ---------------- small helpers ----------------
__device__ __forceinline__ void atomicMaxFloat(float* addr, float val) {
    if (val >= 0.f) atomicMax((int*)addr, __float_as_int(val));
    else            atomicMin((unsigned int*)addr, __float_as_uint(val));
}

__device__ __forceinline__ void red_add_v4(float* p, float4 v) {
    asm volatile("red.global.add.v4.f32 [%0], {%1,%2,%3,%4};"
                 :: "l"(p), "f"(v.x), "f"(v.y), "f"(v.z), "f"(v.w) : "memory");
}

__global__ void fill_kernel(float* __restrict__ p, float v, int n) {
    int i = blockIdx.x * blockDim.x + threadIdx.x;
    if (i < n) p[i] = v;
}

// ---------------- hW GEMM + fused attention logits (FFMA2 / f32x2) ----------------
// Block: 128 threads, 64 nodes. Thread (ng=tid>>3, cg=tid&7) computes a
// 4-node x 8-col tile; columns owned STRIDED: col = j*8 + cg (bank-conflict-free
// W reads). k packed in pairs into 64-bit f32x2 lanes; accumulators are f32x2.
// Relations looped inside the block: h tile loaded once, W_r reloaded per r.
#define HS_STRIDE 66   // even (8B align for b64 reads), 4ng rows -> banks {0,8,16,24}
#define WT_STRIDE 66   // cols j*8+cg -> banks (16j+2cg+k)%32, 8 distinct

__global__ __launch_bounds__(128, 4)
void hw_att_kernel(const float* __restrict__ h,
                   const float* __restrict__ W,
                   const float* __restrict__ a_src,
                   const float* __restrict__ a_dst,
                   float* __restrict__ hW,
                   float* __restrict__ att_s,
                   float* __restrict__ att_d,
                   int N, int R)
{
    __shared__ float hs[64 * HS_STRIDE];   // [node][k]
    __shared__ float Wt[64 * WT_STRIDE];   // [col][k]  (transposed W_r)

    const int tid = threadIdx.x;
    const int n0  = blockIdx.x * 64;
    const int ng  = tid >> 3;   // 0..15, 4 nodes each
    const int cg  = tid & 7;    // 0..7

    // ---- load h tile: 64 nodes x 64 cols (zero-pad OOB) ----
    #pragma unroll
    for (int it = 0; it < 8; it++) {
        int idx4 = it * 128 + tid;          // float4 index 0..1023
        int row  = idx4 >> 4;
        int col  = (idx4 & 15) * 4;
        int n    = n0 + row;
        float4 v = make_float4(0.f, 0.f, 0.f, 0.f);
        if (n < N) v = *(const float4*)&h[(size_t)n * 64 + col];
        float* d = &hs[row * HS_STRIDE + col];
        d[0] = v.x; d[1] = v.y; d[2] = v.z; d[3] = v.w;
    }

    for (int r = 0; r < R; r++) {
        __syncthreads();   // protect Wt from previous iteration's readers
        // ---- load W_r transposed: Wt[col][k] ----
        const float* Wr = W + (size_t)r * 64 * 64;
        #pragma unroll
        for (int it = 0; it < 8; it++) {
            int idx4 = it * 128 + tid;
            int k    = idx4 >> 4;
            int c    = (idx4 & 15) * 4;
            float4 v = *(const float4*)&Wr[k * 64 + c];
            Wt[(c + 0) * WT_STRIDE + k] = v.x;
            Wt[(c + 1) * WT_STRIDE + k] = v.y;
            Wt[(c + 2) * WT_STRIDE + k] = v.z;
            Wt[(c + 3) * WT_STRIDE + k] = v.w;
        }
        __syncthreads();

        // ---- f32x2 outer-product mainloop: acc[i][j] lanes = (even-k, odd-k) ----
        unsigned long long acc[4][8];
        #pragma unroll
        for (int i = 0; i < 4; i++)
            #pragma unroll
            for (int j = 0; j < 8; j++) acc[i][j] = 0ULL;

        #pragma unroll 4
        for (int kp = 0; kp < 32; kp++) {
            const int k = kp * 2;
            unsigned long long hv[4], wv[8];
            #pragma unroll
            for (int i = 0; i < 4; i++)
                hv[i] = *(const unsigned long long*)&hs[(ng * 4 + i) * HS_STRIDE + k];
            #pragma unroll
            for (int j = 0; j < 8; j++)
                wv[j] = *(const unsigned long long*)&Wt[(j * 8 + cg) * WT_STRIDE + k];
            #pragma unroll
            for (int i = 0; i < 4; i++)
                #pragma unroll
                for (int j = 0; j < 8; j++)
                    asm("fma.rn.f32x2 %0, %1, %2, %0;"
                        : "+l"(acc[i][j]) : "l"(hv[i]), "l"(wv[j]));
        }

        // ---- epilogue: horizontal add, fused attention logits, stores ----
        float as[8], ad[8];
        #pragma unroll
        for (int j = 0; j < 8; j++) {
            as[j] = a_src[r * 64 + j * 8 + cg];
            ad[j] = a_dst[r * 64 + j * 8 + cg];
        }

        #pragma unroll
        for (int i = 0; i < 4; i++) {
            int n = n0 + ng * 4 + i;
            float val[8];
            float ps = 0.f, pd = 0.f;
            #pragma unroll
            for (int j = 0; j < 8; j++) {
                float2 p = *(float2*)&acc[i][j];
                val[j] = p.x + p.y;
                ps += val[j] * as[j];
                pd += val[j] * ad[j];
            }
            // reduce over the 8 cg lanes (lane = tid&7 within warp groups of 8)
            #pragma unroll
            for (int o = 4; o >= 1; o >>= 1) {
                ps += __shfl_xor_sync(0xffffffffu, ps, o);
                pd += __shfl_xor_sync(0xffffffffu, pd, o);
            }
            if (n < N) {
                float* o = hW + ((size_t)r * N + n) * 64;
                #pragma unroll
                for (int j = 0; j < 8; j++) o[j * 8 + cg] = val[j];
                if (cg == 0) {
                    att_s[(size_t)r * N + n] = ps;
                    att_d[(size_t)r * N + n] = pd;
                }
            }
        }
    }
}

// ---------------- edge passes ----------------
__global__ void edge_scores_kernel(const int* __restrict__ src, const int* __restrict__ dst,
                                   const int* __restrict__ rel,
                                   const float* __restrict__ att_s, const float* __restrict__ att_d,
                                   float* __restrict__ scores, float* __restrict__ dmax,
                                   int E, int N)
{
    int e = blockIdx.x * blockDim.x + threadIdx.x;
    if (e >= E) return;
    int s = src[e], d = dst[e], r = rel[e];
    float v = att_s[(size_t)r * N + s] + att_d[(size_t)r * N + d];
    v = (v > 0.f) ? v : 0.2f * v;            // leaky_relu
    scores[e] = v;
    atomicMaxFloat(&dmax[d], v);
}

__global__ void edge_exp_kernel(const int* __restrict__ dst,
                                const float* __restrict__ scores, const float* __restrict__ dmax,
                                float* __restrict__ ex, float* __restrict__ dsum, int E)
{
    int e = blockIdx.x * blockDim.x + threadIdx.x;
    if (e >= E) return;
    int d = dst[e];
    float v = expf(scores[e] - dmax[d]);
    ex[e] = v;
    atomicAdd(&dsum[d], v);
}

// 16 threads per edge, float4 vector reductions
__global__ void edge_scatter_kernel(const int* __restrict__ src, const int* __restrict__ dst,
                                    const int* __restrict__ rel,
                                    const float* __restrict__ ex, const float* __restrict__ dsum,
                                    const float* __restrict__ hW,
                                    float* __restrict__ agg, int E, int N)
{
    int t = blockIdx.x * blockDim.x + threadIdx.x;
    int e = t >> 4;
    if (e >= E) return;
    int g = (t & 15) * 4;
    int s = src[e], d = dst[e], r = rel[e];
    float alpha = ex[e] / (dsum[d] + 1e-9f);
    float4 hv = *(const float4*)&hW[((size_t)r * N + s) * 64 + g];
    red_add_v4(&agg[(size_t)d * 64 + g],
               make_float4(alpha * hv.x, alpha * hv.y, alpha * hv.z, alpha * hv.w));
}

__global__ void elu_kernel(float* __restrict__ x, int n) {
    int i = blockIdx.x * blockDim.x + threadIdx.x;
    if (i >= n) return;
    float v = x[i];
    x[i] = (v > 0.f) ? v : expm1f(v);
}

// segment sum of [n,64] rows into out[seg[i]*ostride + ooff + :64]; 16 threads/row
__global__ void segsum_kernel(const float* __restrict__ x, const int* __restrict__ seg,
                              float* __restrict__ out, int n, int ostride, int ooff)
{
    int t = blockIdx.x * blockDim.x + threadIdx.x;
    int i = t >> 4;
    if (i >= n) return;
    int g = (t & 15) * 4;
    int s = seg[i];
    float4 v = *(const float4*)&x[(size_t)i * 64 + g];
    red_add_v4(&out[(size_t)s * ostride + ooff + g], v);
}

// ---------------- MLP head ----------------
__global__ void fc1_kernel(const float* __restrict__ feat, const float* __restrict__ w,
                           const float* __restrict__ b, const float* __restrict__ prelu,
                           float* __restrict__ out)
{
    const int r0 = blockIdx.x * 16;
    __shared__ float fs[16][128];
    for (int i = threadIdx.x; i < 16 * 128; i += blockDim.x)
        fs[i >> 7][i & 127] = feat[(size_t)(r0 + (i >> 7)) * 128 + (i & 127)];
    __syncthreads();

    const int col = threadIdx.x;   // 0..511
    float acc[16];
    #pragma unroll
    for (int j = 0; j < 16; j++) acc[j] = 0.f;
    for (int k = 0; k < 128; k++) {
        float wv = w[k * 512 + col];
        #pragma unroll
        for (int j = 0; j < 16; j++) acc[j] += fs[j][k] * wv;
    }
    float bb = b[col], p = prelu[0];
    #pragma unroll
    for (int j = 0; j < 16; j++) {
        float v = acc[j] + bb;
        out[(size_t)(r0 + j) * 512 + col] = (v > 0.f) ? v : p * v;
    }
}

__global__ void fc2_kernel(const float* __restrict__ hid, const float* __restrict__ w,
                           const float* __restrict__ b, float* __restrict__ out)
{
    const int r0 = blockIdx.x * 16;
    __shared__ float hs[16][512];
    for (int i = threadIdx.x; i < 16 * 512; i += blockDim.x)
        hs[i >> 9][i & 511] = hid[(size_t)(r0 + (i >> 9)) * 512 + (i & 511)];
    __syncthreads();

    const int col = threadIdx.x;
    if (col >= 703) return;
    float acc[16];
    #pragma unroll
    for (int j = 0; j < 16; j++) acc[j] = 0.f;
    for (int k = 0; k < 512; k++) {
        float wv = w[k * 703 + col];
        #pragma unroll
        for (int j = 0; j < 16; j++) acc[j] += hs[j][k] * wv;
    }
    float bb = b[col];
    #pragma unroll
    for (int j = 0; j < 16; j++)
        out[(size_t)(r0 + j) * 703 + col] = acc[j] + bb;
}

// ---------------- launch ----------------
static inline int cdiv(int a, int b) { return (a + b - 1) / b; }

extern "C" void kernel_launch(void* const* d_in, const int* in_sizes, int n_in,
                              void* d_out, int out_size)
{
    const float* node_feats = (const float*)d_in[0];
    const int*   edge_src   = (const int*)  d_in[1];
    const int*   edge_dst   = (const int*)  d_in[2];
    const int*   edge_rel   = (const int*)  d_in[3];
    const int*   node2mol   = (const int*)  d_in[4];
    const int*   rxn_src    = (const int*)  d_in[5];
    const int*   rxn_dst    = (const int*)  d_in[6];
    const int*   rxn_rel    = (const int*)  d_in[7];
    const int*   mol2rxn    = (const int*)  d_in[8];
    const float* W1    = (const float*)d_in[9];
    const float* as1   = (const float*)d_in[10];
    const float* ad1   = (const float*)d_in[11];
    const float* W2    = (const float*)d_in[12];
    const float* as2   = (const float*)d_in[13];
    const float* ad2   = (const float*)d_in[14];
    const float* Wr    = (const float*)d_in[15];
    const float* asr   = (const float*)d_in[16];
    const float* adr   = (const float*)d_in[17];
    const float* w_fc1 = (const float*)d_in[18];
    const float* b_fc1 = (const float*)d_in[19];
    const float* prelu = (const float*)d_in[20];
    const float* w_fc2 = (const float*)d_in[21];
    const float* b_fc2 = (const float*)d_in[22];
    float* out = (float*)d_out;

    float *p_hW, *p_h1, *p_h2, *p_atts, *p_attd, *p_scores, *p_ex,
          *p_max, *p_sum, *p_mol, *p_molr, *p_feat, *p_hid;
    cudaGetSymbolAddress((void**)&p_hW,    g_hW);
    cudaGetSymbolAddress((void**)&p_h1,    g_h1);
    cudaGetSymbolAddress((void**)&p_h2,    g_h2);
    cudaGetSymbolAddress((void**)&p_atts,  g_atts);
    cudaGetSymbolAddress((void**)&p_attd,  g_attd);
    cudaGetSymbolAddress((void**)&p_scores,g_scores);
    cudaGetSymbolAddress((void**)&p_ex,    g_ex);
    cudaGetSymbolAddress((void**)&p_max,   g_max);
    cudaGetSymbolAddress((void**)&p_sum,   g_sum);
    cudaGetSymbolAddress((void**)&p_mol,   g_mol);
    cudaGetSymbolAddress((void**)&p_molr,  g_molr);
    cudaGetSymbolAddress((void**)&p_feat,  g_feat);
    cudaGetSymbolAddress((void**)&p_hid,   g_hid);

    const float NEG_INF = -INFINITY;
    const int TB = 256;

    // ===== atom layer 1 =====
    fill_kernel<<<cdiv(NN, TB), TB>>>(p_max, NEG_INF, NN);
    fill_kernel<<<cdiv(NN, TB), TB>>>(p_sum, 0.f, NN);
    fill_kernel<<<cdiv(NN * DD, TB), TB>>>(p_h1, 0.f, NN * DD);
    hw_att_kernel<<<cdiv(NN, 64), 128>>>(node_feats, W1, as1, ad1,
                                         p_hW, p_atts, p_attd, NN, RM);
    edge_scores_kernel<<<cdiv(NE, TB), TB>>>(edge_src, edge_dst, edge_rel,
                                             p_atts, p_attd, p_scores, p_max, NE, NN);
    edge_exp_kernel<<<cdiv(NE, TB), TB>>>(edge_dst, p_scores, p_max, p_ex, p_sum, NE);
    edge_scatter_kernel<<<cdiv(NE * 16, TB), TB>>>(edge_src, edge_dst, edge_rel,
                                                   p_ex, p_sum, p_hW, p_h1, NE, NN);
    elu_kernel<<<cdiv(NN * DD, TB), TB>>>(p_h1, NN * DD);

    // ===== atom layer 2 =====
    fill_kernel<<<cdiv(NN, TB), TB>>>(p_max, NEG_INF, NN);
    fill_kernel<<<cdiv(NN, TB), TB>>>(p_sum, 0.f, NN);
    fill_kernel<<<cdiv(NN * DD, TB), TB>>>(p_h2, 0.f, NN * DD);
    hw_att_kernel<<<cdiv(NN, 64), 128>>>(p_h1, W2, as2, ad2,
                                         p_hW, p_atts, p_attd, NN, RM);
    edge_scores_kernel<<<cdiv(NE, TB), TB>>>(edge_src, edge_dst, edge_rel,
                                             p_atts, p_attd, p_scores, p_max, NE, NN);
    edge_exp_kernel<<<cdiv(NE, TB), TB>>>(edge_dst, p_scores, p_max, p_ex, p_sum, NE);
    edge_scatter_kernel<<<cdiv(NE * 16, TB), TB>>>(edge_src, edge_dst, edge_rel,
                                                   p_ex, p_sum, p_hW, p_h2, NE, NN);
    elu_kernel<<<cdiv(NN * DD, TB), TB>>>(p_h2, NN * DD);

    // ===== molecule readout =====
    fill_kernel<<<cdiv(NM * DD, TB), TB>>>(p_mol, 0.f, NM * DD);
    segsum_kernel<<<cdiv(NN * 16, TB), TB>>>(p_h2, node2mol, p_mol, NN, 64, 0);

    // ===== reaction-level RGAT =====
    fill_kernel<<<cdiv(NM, TB), TB>>>(p_max, NEG_INF, NM);
    fill_kernel<<<cdiv(NM, TB), TB>>>(p_sum, 0.f, NM);
    fill_kernel<<<cdiv(NM * DD, TB), TB>>>(p_molr, 0.f, NM * DD);
    hw_att_kernel<<<cdiv(NM, 64), 128>>>(p_mol, Wr, asr, adr,
                                         p_hW, p_atts, p_attd, NM, RR);
    edge_scores_kernel<<<cdiv(NRE, TB), TB>>>(rxn_src, rxn_dst, rxn_rel,
                                              p_atts, p_attd, p_scores, p_max, NRE, NM);
    edge_exp_kernel<<<cdiv(NRE, TB), TB>>>(rxn_dst, p_scores, p_max, p_ex, p_sum, NRE);
    edge_scatter_kernel<<<cdiv(NRE * 16, TB), TB>>>(rxn_src, rxn_dst, rxn_rel,
                                                    p_ex, p_sum, p_hW, p_molr, NRE, NM);
    elu_kernel<<<cdiv(NM * DD, TB), TB>>>(p_molr, NM * DD);

    // ===== reaction readout: feat = [segsum(molr) | segsum(mol)] =====
    fill_kernel<<<cdiv(NB * 2 * DD, TB), TB>>>(p_feat, 0.f, NB * 2 * DD);
    segsum_kernel<<<cdiv(NM * 16, TB), TB>>>(p_molr, mol2rxn, p_feat, NM, 128, 0);
    segsum_kernel<<<cdiv(NM * 16, TB), TB>>>(p_mol,  mol2rxn, p_feat, NM, 128, 64);

    // ===== MLP head =====
    fc1_kernel<<<NB / 16, 512>>>(p_feat, w_fc1, b_fc1, prelu, p_hid);
    fc2_kernel<<<NB / 16, 704>>>(p_hid, w_fc2, b_fc2, out);
}

// round 3
// speedup vs baseline: 2.4504x; 1.0282x over previous
#include <cuda_runtime.h>
#include <math.h>
#include <stdint.h>

// ---------------- problem constants ----------------
#define NN      100000
#define NE      800000
#define DD      64
#define RM      8
#define NM      5000
#define NRE     40000
#define RR      4
#define NB      1024
#define DH      512
#define DO      703

// ---------------- scratch ----------------
__device__ float g_hW [(size_t)RM * NN * DD];
__device__ float g_h1 [(size_t)NN * DD];
__device__ float g_h2 [(size_t)NN * DD];
__device__ float g_atts[(size_t)RM * NN];
__device__ float g_attd[(size_t)RM * NN];
__device__ float g_ex  [NE];
__device__ float g_sum [NN];
__device__ float g_B   [16 * 64];
__device__ float g_mol [(size_t)NM * DD];
__device__ float g_molr[(size_t)NM * DD];
__device__ float g_feat[(size_t)NB * 2 * DD];
__device__ float g_hid [(size_t)NB * DH];

__device__ __forceinline__ void red_add_v4(float* p, float4 v) {
    asm volatile("red.global.add.v4.f32 [%0], {%1,%2,%3,%4};"
                 :: "l"(p), "f"(v.x), "f"(v.y), "f"(v.z), "f"(v.w) : "memory");
}

__global__ void fill_kernel(float* __restrict__ p, float v, int n) {
    int i = blockIdx.x * blockDim.x + threadIdx.x;
    if (i < n) p[i] = v;
}

// ---------------- b[r] = W_r @ a_r precompute ----------------
__global__ void prep_b_kernel(const float* __restrict__ W,
                              const float* __restrict__ a_src,
                              const float* __restrict__ a_dst,
                              float* __restrict__ B, int R)
{
    int r = blockIdx.x, d = threadIdx.x;   // 64 threads
    __shared__ float as[64], ad[64];
    as[d] = a_src[r * 64 + d];
    ad[d] = a_dst[r * 64 + d];
    __syncthreads();
    const float* Wr = W + (size_t)r * 4096 + d * 64;
    float s1 = 0.f, s2 = 0.f;
    #pragma unroll 8
    for (int e = 0; e < 64; e++) {
        float w = Wr[e];
        s1 += w * as[e];
        s2 += w * ad[e];
    }
    B[r * 64 + d]       = s1;
    B[(R + r) * 64 + d] = s2;
}

// ---------------- attention logits: att[r,n] = h[n] . B[r] ----------------
template<int R>
__global__ void att_kernel(const float* __restrict__ h, const float* __restrict__ B,
                           float* __restrict__ att_s, float* __restrict__ att_d, int N)
{
    __shared__ float Bs[2 * R * 64];
    const int tid = threadIdx.x;   // 128
    for (int i = tid; i < 2 * R * 64; i += 128) Bs[i] = B[i];
    __syncthreads();
    int n = blockIdx.x * 128 + tid;
    if (n >= N) return;
    float acc[2 * R];
    #pragma unroll
    for (int rr = 0; rr < 2 * R; rr++) acc[rr] = 0.f;
    const float4* hp = (const float4*)&h[(size_t)n * 64];
    #pragma unroll
    for (int d4 = 0; d4 < 16; d4++) {
        float4 hv = hp[d4];
        #pragma unroll
        for (int rr = 0; rr < 2 * R; rr++) {
            float4 b = *(const float4*)&Bs[rr * 64 + d4 * 4];
            acc[rr] += hv.x * b.x + hv.y * b.y + hv.z * b.z + hv.w * b.w;
        }
    }
    #pragma unroll
    for (int r = 0; r < R; r++) {
        att_s[(size_t)r * N + n] = acc[r];
        att_d[(size_t)r * N + n] = acc[R + r];
    }
}

// ---------------- hW GEMM (FFMA2, contiguous-col epilogue) ----------------
// 128 threads = 16 node-groups x 8 col-groups; thread owns 4 nodes x cols
// [cg*8, cg*8+8). Wt rows permuted: column c stored at row (c&7)*8 + (c>>3),
// so inner-loop smem addressing (row j*8+cg) is conflict-free as before.
#define HS_STRIDE 66
#define WT_STRIDE 66

__global__ __launch_bounds__(128, 4)
void hw_gemm_kernel(const float* __restrict__ h,
                    const float* __restrict__ W,
                    float* __restrict__ hW,
                    int N, int R)
{
    __shared__ float hs[64 * HS_STRIDE];
    __shared__ float Wt[64 * WT_STRIDE];

    const int tid = threadIdx.x;
    const int n0  = blockIdx.x * 64;
    const int ng  = tid >> 3;
    const int cg  = tid & 7;

    #pragma unroll
    for (int it = 0; it < 8; it++) {
        int idx4 = it * 128 + tid;
        int row  = idx4 >> 4;
        int col  = (idx4 & 15) * 4;
        int n    = n0 + row;
        float4 v = make_float4(0.f, 0.f, 0.f, 0.f);
        if (n < N) v = *(const float4*)&h[(size_t)n * 64 + col];
        float* d = &hs[row * HS_STRIDE + col];
        d[0] = v.x; d[1] = v.y; d[2] = v.z; d[3] = v.w;
    }

    for (int r = 0; r < R; r++) {
        __syncthreads();
        const float* Wr = W + (size_t)r * 4096;
        #pragma unroll
        for (int it = 0; it < 8; it++) {
            int idx4 = it * 128 + tid;
            int k    = idx4 >> 4;
            int c    = (idx4 & 15) * 4;
            float4 v = *(const float4*)&Wr[k * 64 + c];
            Wt[(((c + 0) & 7) * 8 + ((c + 0) >> 3)) * WT_STRIDE + k] = v.x;
            Wt[(((c + 1) & 7) * 8 + ((c + 1) >> 3)) * WT_STRIDE + k] = v.y;
            Wt[(((c + 2) & 7) * 8 + ((c + 2) >> 3)) * WT_STRIDE + k] = v.z;
            Wt[(((c + 3) & 7) * 8 + ((c + 3) >> 3)) * WT_STRIDE + k] = v.w;
        }
        __syncthreads();

        unsigned long long acc[4][8];
        #pragma unroll
        for (int i = 0; i < 4; i++)
            #pragma unroll
            for (int j = 0; j < 8; j++) acc[i][j] = 0ULL;

        #pragma unroll 4
        for (int kp = 0; kp < 32; kp++) {
            const int k = kp * 2;
            unsigned long long hv[4], wv[8];
            #pragma unroll
            for (int i = 0; i < 4; i++)
                hv[i] = *(const unsigned long long*)&hs[(ng * 4 + i) * HS_STRIDE + k];
            #pragma unroll
            for (int j = 0; j < 8; j++)
                wv[j] = *(const unsigned long long*)&Wt[(j * 8 + cg) * WT_STRIDE + k];
            #pragma unroll
            for (int i = 0; i < 4; i++)
                #pragma unroll
                for (int j = 0; j < 8; j++)
                    asm("fma.rn.f32x2 %0, %1, %2, %0;"
                        : "+l"(acc[i][j]) : "l"(hv[i]), "l"(wv[j]));
        }

        // epilogue: thread's val[j] is column cg*8+j -> 2 coalesced STG.128 / node
        #pragma unroll
        for (int i = 0; i < 4; i++) {
            int n = n0 + ng * 4 + i;
            if (n < N) {
                float v[8];
                #pragma unroll
                for (int j = 0; j < 8; j++) {
                    float2 p = *(float2*)&acc[i][j];
                    v[j] = p.x + p.y;
                }
                float* o = hW + ((size_t)r * N + n) * 64 + cg * 8;
                *(float4*)(o)     = make_float4(v[0], v[1], v[2], v[3]);
                *(float4*)(o + 4) = make_float4(v[4], v[5], v[6], v[7]);
            }
        }
    }
}

// ---------------- edge passes (no max pass; softmax is shift-invariant) ----------------
__global__ void edge_pass1_kernel(const int* __restrict__ src, const int* __restrict__ dst,
                                  const int* __restrict__ rel,
                                  const float* __restrict__ att_s, const float* __restrict__ att_d,
                                  float* __restrict__ ex, float* __restrict__ dsum,
                                  int E, int N)
{
    int e = blockIdx.x * blockDim.x + threadIdx.x;
    if (e >= E) return;
    int s = src[e], d = dst[e], r = rel[e];
    float v = att_s[(size_t)r * N + s] + att_d[(size_t)r * N + d];
    v = (v > 0.f) ? v : 0.2f * v;
    float x = __expf(v);
    ex[e] = x;
    atomicAdd(&dsum[d], x);
}

__global__ void edge_scatter_kernel(const int* __restrict__ src, const int* __restrict__ dst,
                                    const int* __restrict__ rel,
                                    const float* __restrict__ ex, const float* __restrict__ dsum,
                                    const float* __restrict__ hW,
                                    float* __restrict__ agg, int E, int N)
{
    int t = blockIdx.x * blockDim.x + threadIdx.x;
    int e = t >> 4;
    if (e >= E) return;
    int g = (t & 15) * 4;
    int s = src[e], d = dst[e], r = rel[e];
    float alpha = ex[e] / (dsum[d] + 1e-9f);
    float4 hv = *(const float4*)&hW[((size_t)r * N + s) * 64 + g];
    red_add_v4(&agg[(size_t)d * 64 + g],
               make_float4(alpha * hv.x, alpha * hv.y, alpha * hv.z, alpha * hv.w));
}

__global__ void elu_kernel(float* __restrict__ x, int n) {
    int i = blockIdx.x * blockDim.x + threadIdx.x;
    if (i >= n) return;
    float v = x[i];
    x[i] = (v > 0.f) ? v : expm1f(v);
}

__global__ void segsum_kernel(const float* __restrict__ x, const int* __restrict__ seg,
                              float* __restrict__ out, int n, int ostride, int ooff)
{
    int t = blockIdx.x * blockDim.x + threadIdx.x;
    int i = t >> 4;
    if (i >= n) return;
    int g = (t & 15) * 4;
    int s = seg[i];
    float4 v = *(const float4*)&x[(size_t)i * 64 + g];
    red_add_v4(&out[(size_t)s * ostride + ooff + g], v);
}

// ---------------- MLP head ----------------
__global__ void fc1_kernel(const float* __restrict__ feat, const float* __restrict__ w,
                           const float* __restrict__ b, const float* __restrict__ prelu,
                           float* __restrict__ out)
{
    const int r0 = blockIdx.x * 16;
    __shared__ float fs[16][128];
    for (int i = threadIdx.x; i < 16 * 128; i += blockDim.x)
        fs[i >> 7][i & 127] = feat[(size_t)(r0 + (i >> 7)) * 128 + (i & 127)];
    __syncthreads();
    const int col = threadIdx.x;
    float acc[16];
    #pragma unroll
    for (int j = 0; j < 16; j++) acc[j] = 0.f;
    for (int k = 0; k < 128; k++) {
        float wv = w[k * 512 + col];
        #pragma unroll
        for (int j = 0; j < 16; j++) acc[j] += fs[j][k] * wv;
    }
    float bb = b[col], p = prelu[0];
    #pragma unroll
    for (int j = 0; j < 16; j++) {
        float v = acc[j] + bb;
        out[(size_t)(r0 + j) * 512 + col] = (v > 0.f) ? v : p * v;
    }
}

__global__ void fc2_kernel(const float* __restrict__ hid, const float* __restrict__ w,
                           const float* __restrict__ b, float* __restrict__ out)
{
    const int r0 = blockIdx.x * 16;
    __shared__ float hs[16][512];
    for (int i = threadIdx.x; i < 16 * 512; i += blockDim.x)
        hs[i >> 9][i & 511] = hid[(size_t)(r0 + (i >> 9)) * 512 + (i & 511)];
    __syncthreads();
    const int col = threadIdx.x;
    if (col >= 703) return;
    float acc[16];
    #pragma unroll
    for (int j = 0; j < 16; j++) acc[j] = 0.f;
    for (int k = 0; k < 512; k++) {
        float wv = w[k * 703 + col];
        #pragma unroll
        for (int j = 0; j < 16; j++) acc[j] += hs[j][k] * wv;
    }
    float bb = b[col];
    #pragma unroll
    for (int j = 0; j < 16; j++)
        out[(size_t)(r0 + j) * 703 + col] = acc[j] + bb;
}

// ---------------- launch ----------------
static inline int cdiv(int a, int b) { return (a + b - 1) / b; }

extern "C" void kernel_launch(void* const* d_in, const int* in_sizes, int n_in,
                              void* d_out, int out_size)
{
    const float* node_feats = (const float*)d_in[0];
    const int*   edge_src   = (const int*)  d_in[1];
    const int*   edge_dst   = (const int*)  d_in[2];
    const int*   edge_rel   = (const int*)  d_in[3];
    const int*   node2mol   = (const int*)  d_in[4];
    const int*   rxn_src    = (const int*)  d_in[5];
    const int*   rxn_dst    = (const int*)  d_in[6];
    const int*   rxn_rel    = (const int*)  d_in[7];
    const int*   mol2rxn    = (const int*)  d_in[8];
    const float* W1    = (const float*)d_in[9];
    const float* as1   = (const float*)d_in[10];
    const float* ad1   = (const float*)d_in[11];
    const float* W2    = (const float*)d_in[12];
    const float* as2   = (const float*)d_in[13];
    const float* ad2   = (const float*)d_in[14];
    const float* Wr    = (const float*)d_in[15];
    const float* asr   = (const float*)d_in[16];
    const float* adr   = (const float*)d_in[17];
    const float* w_fc1 = (const float*)d_in[18];
    const float* b_fc1 = (const float*)d_in[19];
    const float* prelu = (const float*)d_in[20];
    const float* w_fc2 = (const float*)d_in[21];
    const float* b_fc2 = (const float*)d_in[22];
    float* out = (float*)d_out;

    float *p_hW, *p_h1, *p_h2, *p_atts, *p_attd, *p_ex, *p_sum, *p_B,
          *p_mol, *p_molr, *p_feat, *p_hid;
    cudaGetSymbolAddress((void**)&p_hW,   g_hW);
    cudaGetSymbolAddress((void**)&p_h1,   g_h1);
    cudaGetSymbolAddress((void**)&p_h2,   g_h2);
    cudaGetSymbolAddress((void**)&p_atts, g_atts);
    cudaGetSymbolAddress((void**)&p_attd, g_attd);
    cudaGetSymbolAddress((void**)&p_ex,   g_ex);
    cudaGetSymbolAddress((void**)&p_sum,  g_sum);
    cudaGetSymbolAddress((void**)&p_B,    g_B);
    cudaGetSymbolAddress((void**)&p_mol,  g_mol);
    cudaGetSymbolAddress((void**)&p_molr, g_molr);
    cudaGetSymbolAddress((void**)&p_feat, g_feat);
    cudaGetSymbolAddress((void**)&p_hid,  g_hid);

    const int TB = 256;

    // ===== atom layer 1 =====
    fill_kernel<<<cdiv(NN, TB), TB>>>(p_sum, 0.f, NN);
    fill_kernel<<<cdiv(NN * DD, TB), TB>>>(p_h1, 0.f, NN * DD);
    prep_b_kernel<<<RM, 64>>>(W1, as1, ad1, p_B, RM);
    att_kernel<RM><<<cdiv(NN, 128), 128>>>(node_feats, p_B, p_atts, p_attd, NN);
    hw_gemm_kernel<<<cdiv(NN, 64), 128>>>(node_feats, W1, p_hW, NN, RM);
    edge_pass1_kernel<<<cdiv(NE, TB), TB>>>(edge_src, edge_dst, edge_rel,
                                            p_atts, p_attd, p_ex, p_sum, NE, NN);
    edge_scatter_kernel<<<cdiv(NE * 16, TB), TB>>>(edge_src, edge_dst, edge_rel,
                                                   p_ex, p_sum, p_hW, p_h1, NE, NN);
    elu_kernel<<<cdiv(NN * DD, TB), TB>>>(p_h1, NN * DD);

    // ===== atom layer 2 =====
    fill_kernel<<<cdiv(NN, TB), TB>>>(p_sum, 0.f, NN);
    fill_kernel<<<cdiv(NN * DD, TB), TB>>>(p_h2, 0.f, NN * DD);
    prep_b_kernel<<<RM, 64>>>(W2, as2, ad2, p_B, RM);
    att_kernel<RM><<<cdiv(NN, 128), 128>>>(p_h1, p_B, p_atts, p_attd, NN);
    hw_gemm_kernel<<<cdiv(NN, 64), 128>>>(p_h1, W2, p_hW, NN, RM);
    edge_pass1_kernel<<<cdiv(NE, TB), TB>>>(edge_src, edge_dst, edge_rel,
                                            p_atts, p_attd, p_ex, p_sum, NE, NN);
    edge_scatter_kernel<<<cdiv(NE * 16, TB), TB>>>(edge_src, edge_dst, edge_rel,
                                                   p_ex, p_sum, p_hW, p_h2, NE, NN);
    elu_kernel<<<cdiv(NN * DD, TB), TB>>>(p_h2, NN * DD);

    // ===== molecule readout =====
    fill_kernel<<<cdiv(NM * DD, TB), TB>>>(p_mol, 0.f, NM * DD);
    segsum_kernel<<<cdiv(NN * 16, TB), TB>>>(p_h2, node2mol, p_mol, NN, 64, 0);

    // ===== reaction-level RGAT =====
    fill_kernel<<<cdiv(NM, TB), TB>>>(p_sum, 0.f, NM);
    fill_kernel<<<cdiv(NM * DD, TB), TB>>>(p_molr, 0.f, NM * DD);
    prep_b_kernel<<<RR, 64>>>(Wr, asr, adr, p_B, RR);
    att_kernel<RR><<<cdiv(NM, 128), 128>>>(p_mol, p_B, p_atts, p_attd, NM);
    hw_gemm_kernel<<<cdiv(NM, 64), 128>>>(p_mol, Wr, p_hW, NM, RR);
    edge_pass1_kernel<<<cdiv(NRE, TB), TB>>>(rxn_src, rxn_dst, rxn_rel,
                                             p_atts, p_attd, p_ex, p_sum, NRE, NM);
    edge_scatter_kernel<<<cdiv(NRE * 16, TB), TB>>>(rxn_src, rxn_dst, rxn_rel,
                                                    p_ex, p_sum, p_hW, p_molr, NRE, NM);
    elu_kernel<<<cdiv(NM * DD, TB), TB>>>(p_molr, NM * DD);

    // ===== reaction readout =====
    fill_kernel<<<cdiv(NB * 2 * DD, TB), TB>>>(p_feat, 0.f, NB * 2 * DD);
    segsum_kernel<<<cdiv(NM * 16, TB), TB>>>(p_molr, mol2rxn, p_feat, NM, 128, 0);
    segsum_kernel<<<cdiv(NM * 16, TB), TB>>>(p_mol,  mol2rxn, p_feat, NM, 128, 64);

    // ===== MLP head =====
    fc1_kernel<<<NB / 16, 512>>>(p_feat, w_fc1, b_fc1, prelu, p_hid);
    fc2_kernel<<<NB / 16, 704>>>(p_hid, w_fc2, b_fc2, out);
}

// round 4
// speedup vs baseline: 2.4909x; 1.0165x over previous
#include <cuda_runtime.h>
#include <math.h>
#include <stdint.h>

// ---------------- problem constants ----------------
#define NN      100000
#define NE      800000
#define DD      64
#define RM      8
#define NM      5000
#define NRE     40000
#define RR      4
#define NB      1024
#define DH      512
#define DO      703

// ---------------- scratch ----------------
__device__ float g_hW [(size_t)RM * NN * DD];
__device__ float g_h1 [(size_t)NN * DD];
__device__ float g_h2 [(size_t)NN * DD];
__device__ float g_atts[(size_t)RM * NN];
__device__ float g_attd[(size_t)RM * NN];
__device__ float g_ex  [NE];
__device__ float g_sum [NN];
__device__ float g_B   [16 * 64];
__device__ float g_mol [(size_t)NM * DD];
__device__ float g_molr[(size_t)NM * DD];
__device__ float g_feat[(size_t)NB * 2 * DD];
__device__ float g_hid [(size_t)NB * DH];

__device__ __forceinline__ void red_add_v4(float* p, float4 v) {
    asm volatile("red.global.add.v4.f32 [%0], {%1,%2,%3,%4};"
                 :: "l"(p), "f"(v.x), "f"(v.y), "f"(v.z), "f"(v.w) : "memory");
}

__global__ void fill_kernel(float* __restrict__ p, float v, int n) {
    int i = blockIdx.x * blockDim.x + threadIdx.x;
    if (i < n) p[i] = v;
}

// ---------------- b[r] = W_r @ a_r precompute ----------------
__global__ void prep_b_kernel(const float* __restrict__ W,
                              const float* __restrict__ a_src,
                              const float* __restrict__ a_dst,
                              float* __restrict__ B, int R)
{
    int r = blockIdx.x, d = threadIdx.x;   // 64 threads
    __shared__ float as[64], ad[64];
    as[d] = a_src[r * 64 + d];
    ad[d] = a_dst[r * 64 + d];
    __syncthreads();
    const float* Wr = W + (size_t)r * 4096 + d * 64;
    float s1 = 0.f, s2 = 0.f;
    #pragma unroll 8
    for (int e = 0; e < 64; e++) {
        float w = Wr[e];
        s1 += w * as[e];
        s2 += w * ad[e];
    }
    B[r * 64 + d]       = s1;
    B[(R + r) * 64 + d] = s2;
}

// ---------------- attention logits: att[r,n] = h[n] . B[r] ----------------
template<int R>
__global__ void att_kernel(const float* __restrict__ h, const float* __restrict__ B,
                           float* __restrict__ att_s, float* __restrict__ att_d, int N)
{
    __shared__ float Bs[2 * R * 64];
    const int tid = threadIdx.x;   // 128
    for (int i = tid; i < 2 * R * 64; i += 128) Bs[i] = B[i];
    __syncthreads();
    int n = blockIdx.x * 128 + tid;
    if (n >= N) return;
    float acc[2 * R];
    #pragma unroll
    for (int rr = 0; rr < 2 * R; rr++) acc[rr] = 0.f;
    const float4* hp = (const float4*)&h[(size_t)n * 64];
    #pragma unroll
    for (int d4 = 0; d4 < 16; d4++) {
        float4 hv = hp[d4];
        #pragma unroll
        for (int rr = 0; rr < 2 * R; rr++) {
            float4 b = *(const float4*)&Bs[rr * 64 + d4 * 4];
            acc[rr] += hv.x * b.x + hv.y * b.y + hv.z * b.z + hv.w * b.w;
        }
    }
    #pragma unroll
    for (int r = 0; r < R; r++) {
        att_s[(size_t)r * N + n] = acc[r];
        att_d[(size_t)r * N + n] = acc[R + r];
    }
}

// ---------------- hW GEMM (FFMA2, 8x8 register tile) ----------------
// 128 threads = 16 ng x 8 cg. Thread owns 8 nodes (n0 + i*16 + ng, strided so
// a warp's 4 ng hit consecutive smem rows -> conflict-free) x 8 contiguous
// cols [cg*8, cg*8+8). Per kp: 16 LDS.64 per 64 FFMA2-lanes = crossbar/FMA
// balanced. W transposed+permuted in smem as before (row (c&7)*8+(c>>3)).
#define HS_STRIDE 66
#define WT_STRIDE 66

__global__ __launch_bounds__(128, 2)
void hw_gemm_kernel(const float* __restrict__ h,
                    const float* __restrict__ W,
                    float* __restrict__ hW,
                    int N, int R)
{
    __shared__ float hs[128 * HS_STRIDE];   // 33.8 KB
    __shared__ float Wt[64 * WT_STRIDE];    // 16.9 KB

    const int tid = threadIdx.x;
    const int n0  = blockIdx.x * 128;
    const int ng  = tid >> 3;   // 0..15
    const int cg  = tid & 7;    // 0..7

    // ---- load h tile: 128 nodes ----
    #pragma unroll
    for (int it = 0; it < 16; it++) {
        int idx4 = it * 128 + tid;          // float4 index 0..2047
        int row  = idx4 >> 4;
        int col  = (idx4 & 15) * 4;
        int n    = n0 + row;
        float4 v = make_float4(0.f, 0.f, 0.f, 0.f);
        if (n < N) v = *(const float4*)&h[(size_t)n * 64 + col];
        float* d = &hs[row * HS_STRIDE + col];
        d[0] = v.x; d[1] = v.y; d[2] = v.z; d[3] = v.w;
    }

    for (int r = 0; r < R; r++) {
        __syncthreads();
        const float* Wr = W + (size_t)r * 4096;
        #pragma unroll
        for (int it = 0; it < 8; it++) {
            int idx4 = it * 128 + tid;
            int k    = idx4 >> 4;
            int c    = (idx4 & 15) * 4;
            float4 v = *(const float4*)&Wr[k * 64 + c];
            Wt[(((c + 0) & 7) * 8 + ((c + 0) >> 3)) * WT_STRIDE + k] = v.x;
            Wt[(((c + 1) & 7) * 8 + ((c + 1) >> 3)) * WT_STRIDE + k] = v.y;
            Wt[(((c + 2) & 7) * 8 + ((c + 2) >> 3)) * WT_STRIDE + k] = v.z;
            Wt[(((c + 3) & 7) * 8 + ((c + 3) >> 3)) * WT_STRIDE + k] = v.w;
        }
        __syncthreads();

        unsigned long long acc[8][8];
        #pragma unroll
        for (int i = 0; i < 8; i++)
            #pragma unroll
            for (int j = 0; j < 8; j++) acc[i][j] = 0ULL;

        #pragma unroll 2
        for (int kp = 0; kp < 32; kp++) {
            const int k = kp * 2;
            unsigned long long hv[8], wv[8];
            #pragma unroll
            for (int i = 0; i < 8; i++)
                hv[i] = *(const unsigned long long*)&hs[(i * 16 + ng) * HS_STRIDE + k];
            #pragma unroll
            for (int j = 0; j < 8; j++)
                wv[j] = *(const unsigned long long*)&Wt[(j * 8 + cg) * WT_STRIDE + k];
            #pragma unroll
            for (int i = 0; i < 8; i++)
                #pragma unroll
                for (int j = 0; j < 8; j++)
                    asm("fma.rn.f32x2 %0, %1, %2, %0;"
                        : "+l"(acc[i][j]) : "l"(hv[i]), "l"(wv[j]));
        }

        // epilogue: 2 coalesced STG.128 per node
        #pragma unroll
        for (int i = 0; i < 8; i++) {
            int n = n0 + i * 16 + ng;
            if (n < N) {
                float v[8];
                #pragma unroll
                for (int j = 0; j < 8; j++) {
                    float2 p = *(float2*)&acc[i][j];
                    v[j] = p.x + p.y;
                }
                float* o = hW + ((size_t)r * N + n) * 64 + cg * 8;
                *(float4*)(o)     = make_float4(v[0], v[1], v[2], v[3]);
                *(float4*)(o + 4) = make_float4(v[4], v[5], v[6], v[7]);
            }
        }
    }
}

// ---------------- edge passes ----------------
__global__ void edge_pass1_kernel(const int* __restrict__ src, const int* __restrict__ dst,
                                  const int* __restrict__ rel,
                                  const float* __restrict__ att_s, const float* __restrict__ att_d,
                                  float* __restrict__ ex, float* __restrict__ dsum,
                                  int E, int N)
{
    int e = blockIdx.x * blockDim.x + threadIdx.x;
    if (e >= E) return;
    int s = src[e], d = dst[e], r = rel[e];
    float v = att_s[(size_t)r * N + s] + att_d[(size_t)r * N + d];
    v = (v > 0.f) ? v : 0.2f * v;
    float x = __expf(v);
    ex[e] = x;
    atomicAdd(&dsum[d], x);
}

__global__ void edge_scatter_kernel(const int* __restrict__ src, const int* __restrict__ dst,
                                    const int* __restrict__ rel,
                                    const float* __restrict__ ex, const float* __restrict__ dsum,
                                    const float* __restrict__ hW,
                                    float* __restrict__ agg, int E, int N)
{
    int t = blockIdx.x * blockDim.x + threadIdx.x;
    int e = t >> 4;
    if (e >= E) return;
    int g = (t & 15) * 4;
    int s = src[e], d = dst[e], r = rel[e];
    float alpha = ex[e] / (dsum[d] + 1e-9f);
    float4 hv = *(const float4*)&hW[((size_t)r * N + s) * 64 + g];
    red_add_v4(&agg[(size_t)d * 64 + g],
               make_float4(alpha * hv.x, alpha * hv.y, alpha * hv.z, alpha * hv.w));
}

__global__ void elu_kernel(float* __restrict__ x, int n) {
    int i = blockIdx.x * blockDim.x + threadIdx.x;
    if (i >= n) return;
    float v = x[i];
    x[i] = (v > 0.f) ? v : expm1f(v);
}

__global__ void segsum_kernel(const float* __restrict__ x, const int* __restrict__ seg,
                              float* __restrict__ out, int n, int ostride, int ooff)
{
    int t = blockIdx.x * blockDim.x + threadIdx.x;
    int i = t >> 4;
    if (i >= n) return;
    int g = (t & 15) * 4;
    int s = seg[i];
    float4 v = *(const float4*)&x[(size_t)i * 64 + g];
    red_add_v4(&out[(size_t)s * ostride + ooff + g], v);
}

// ---------------- MLP head ----------------
// fc1: grid (NB/16, 4), block 128: 16 rows x 128-col chunk.
__global__ void fc1_kernel(const float* __restrict__ feat, const float* __restrict__ w,
                           const float* __restrict__ b, const float* __restrict__ prelu,
                           float* __restrict__ out)
{
    const int r0 = blockIdx.x * 16;
    const int c0 = blockIdx.y * 128;
    __shared__ float fs[16][128];
    #pragma unroll
    for (int it = 0; it < 4; it++) {
        int idx4 = it * 128 + threadIdx.x;      // 512 float4
        int row = idx4 >> 5, col = (idx4 & 31) * 4;
        *(float4*)&fs[row][col] = *(const float4*)&feat[(size_t)(r0 + row) * 128 + col];
    }
    __syncthreads();
    const int col = c0 + threadIdx.x;
    float acc[16];
    #pragma unroll
    for (int j = 0; j < 16; j++) acc[j] = 0.f;
    #pragma unroll 4
    for (int k = 0; k < 128; k++) {
        float wv = w[k * 512 + col];
        #pragma unroll
        for (int j = 0; j < 16; j++) acc[j] += fs[j][k] * wv;
    }
    float bb = b[col], p = prelu[0];
    #pragma unroll
    for (int j = 0; j < 16; j++) {
        float v = acc[j] + bb;
        out[(size_t)(r0 + j) * 512 + col] = (v > 0.f) ? v : p * v;
    }
}

// fc2: grid (NB/16, 6), block 128: 16 rows x 128-col chunk (last chunk 63 cols).
__global__ void fc2_kernel(const float* __restrict__ hid, const float* __restrict__ w,
                           const float* __restrict__ b, float* __restrict__ out)
{
    const int r0 = blockIdx.x * 16;
    const int c0 = blockIdx.y * 128;
    __shared__ float hs[16][512];
    #pragma unroll
    for (int it = 0; it < 16; it++) {
        int idx4 = it * 128 + threadIdx.x;      // 2048 float4
        int row = idx4 >> 7, col = (idx4 & 127) * 4;
        *(float4*)&hs[row][col] = *(const float4*)&hid[(size_t)(r0 + row) * 512 + col];
    }
    __syncthreads();
    const int col = c0 + threadIdx.x;
    if (col >= DO) return;
    float acc[16];
    #pragma unroll
    for (int j = 0; j < 16; j++) acc[j] = 0.f;
    #pragma unroll 4
    for (int k = 0; k < 512; k++) {
        float wv = w[k * DO + col];
        #pragma unroll
        for (int j = 0; j < 16; j++) acc[j] += hs[j][k] * wv;
    }
    float bb = b[col];
    #pragma unroll
    for (int j = 0; j < 16; j++)
        out[(size_t)(r0 + j) * DO + col] = acc[j] + bb;
}

// ---------------- launch ----------------
static inline int cdiv(int a, int b) { return (a + b - 1) / b; }

extern "C" void kernel_launch(void* const* d_in, const int* in_sizes, int n_in,
                              void* d_out, int out_size)
{
    const float* node_feats = (const float*)d_in[0];
    const int*   edge_src   = (const int*)  d_in[1];
    const int*   edge_dst   = (const int*)  d_in[2];
    const int*   edge_rel   = (const int*)  d_in[3];
    const int*   node2mol   = (const int*)  d_in[4];
    const int*   rxn_src    = (const int*)  d_in[5];
    const int*   rxn_dst    = (const int*)  d_in[6];
    const int*   rxn_rel    = (const int*)  d_in[7];
    const int*   mol2rxn    = (const int*)  d_in[8];
    const float* W1    = (const float*)d_in[9];
    const float* as1   = (const float*)d_in[10];
    const float* ad1   = (const float*)d_in[11];
    const float* W2    = (const float*)d_in[12];
    const float* as2   = (const float*)d_in[13];
    const float* ad2   = (const float*)d_in[14];
    const float* Wr    = (const float*)d_in[15];
    const float* asr   = (const float*)d_in[16];
    const float* adr   = (const float*)d_in[17];
    const float* w_fc1 = (const float*)d_in[18];
    const float* b_fc1 = (const float*)d_in[19];
    const float* prelu = (const float*)d_in[20];
    const float* w_fc2 = (const float*)d_in[21];
    const float* b_fc2 = (const float*)d_in[22];
    float* out = (float*)d_out;

    float *p_hW, *p_h1, *p_h2, *p_atts, *p_attd, *p_ex, *p_sum, *p_B,
          *p_mol, *p_molr, *p_feat, *p_hid;
    cudaGetSymbolAddress((void**)&p_hW,   g_hW);
    cudaGetSymbolAddress((void**)&p_h1,   g_h1);
    cudaGetSymbolAddress((void**)&p_h2,   g_h2);
    cudaGetSymbolAddress((void**)&p_atts, g_atts);
    cudaGetSymbolAddress((void**)&p_attd, g_attd);
    cudaGetSymbolAddress((void**)&p_ex,   g_ex);
    cudaGetSymbolAddress((void**)&p_sum,  g_sum);
    cudaGetSymbolAddress((void**)&p_B,    g_B);
    cudaGetSymbolAddress((void**)&p_mol,  g_mol);
    cudaGetSymbolAddress((void**)&p_molr, g_molr);
    cudaGetSymbolAddress((void**)&p_feat, g_feat);
    cudaGetSymbolAddress((void**)&p_hid,  g_hid);

    const int TB = 256;

    // ===== atom layer 1 =====
    fill_kernel<<<cdiv(NN, TB), TB>>>(p_sum, 0.f, NN);
    fill_kernel<<<cdiv(NN * DD, TB), TB>>>(p_h1, 0.f, NN * DD);
    prep_b_kernel<<<RM, 64>>>(W1, as1, ad1, p_B, RM);
    att_kernel<RM><<<cdiv(NN, 128), 128>>>(node_feats, p_B, p_atts, p_attd, NN);
    hw_gemm_kernel<<<cdiv(NN, 128), 128>>>(node_feats, W1, p_hW, NN, RM);
    edge_pass1_kernel<<<cdiv(NE, TB), TB>>>(edge_src, edge_dst, edge_rel,
                                            p_atts, p_attd, p_ex, p_sum, NE, NN);
    edge_scatter_kernel<<<cdiv(NE * 16, TB), TB>>>(edge_src, edge_dst, edge_rel,
                                                   p_ex, p_sum, p_hW, p_h1, NE, NN);
    elu_kernel<<<cdiv(NN * DD, TB), TB>>>(p_h1, NN * DD);

    // ===== atom layer 2 =====
    fill_kernel<<<cdiv(NN, TB), TB>>>(p_sum, 0.f, NN);
    fill_kernel<<<cdiv(NN * DD, TB), TB>>>(p_h2, 0.f, NN * DD);
    prep_b_kernel<<<RM, 64>>>(W2, as2, ad2, p_B, RM);
    att_kernel<RM><<<cdiv(NN, 128), 128>>>(p_h1, p_B, p_atts, p_attd, NN);
    hw_gemm_kernel<<<cdiv(NN, 128), 128>>>(p_h1, W2, p_hW, NN, RM);
    edge_pass1_kernel<<<cdiv(NE, TB), TB>>>(edge_src, edge_dst, edge_rel,
                                            p_atts, p_attd, p_ex, p_sum, NE, NN);
    edge_scatter_kernel<<<cdiv(NE * 16, TB), TB>>>(edge_src, edge_dst, edge_rel,
                                                   p_ex, p_sum, p_hW, p_h2, NE, NN);
    elu_kernel<<<cdiv(NN * DD, TB), TB>>>(p_h2, NN * DD);

    // ===== molecule readout =====
    fill_kernel<<<cdiv(NM * DD, TB), TB>>>(p_mol, 0.f, NM * DD);
    segsum_kernel<<<cdiv(NN * 16, TB), TB>>>(p_h2, node2mol, p_mol, NN, 64, 0);

    // ===== reaction-level RGAT =====
    fill_kernel<<<cdiv(NM, TB), TB>>>(p_sum, 0.f, NM);
    fill_kernel<<<cdiv(NM * DD, TB), TB>>>(p_molr, 0.f, NM * DD);
    prep_b_kernel<<<RR, 64>>>(Wr, asr, adr, p_B, RR);
    att_kernel<RR><<<cdiv(NM, 128), 128>>>(p_mol, p_B, p_atts, p_attd, NM);
    hw_gemm_kernel<<<cdiv(NM, 128), 128>>>(p_mol, Wr, p_hW, NM, RR);
    edge_pass1_kernel<<<cdiv(NRE, TB), TB>>>(rxn_src, rxn_dst, rxn_rel,
                                             p_atts, p_attd, p_ex, p_sum, NRE, NM);
    edge_scatter_kernel<<<cdiv(NRE * 16, TB), TB>>>(rxn_src, rxn_dst, rxn_rel,
                                                    p_ex, p_sum, p_hW, p_molr, NRE, NM);
    elu_kernel<<<cdiv(NM * DD, TB), TB>>>(p_molr, NM * DD);

    // ===== reaction readout =====
    fill_kernel<<<cdiv(NB * 2 * DD, TB), TB>>>(p_feat, 0.f, NB * 2 * DD);
    segsum_kernel<<<cdiv(NM * 16, TB), TB>>>(p_molr, mol2rxn, p_feat, NM, 128, 0);
    segsum_kernel<<<cdiv(NM * 16, TB), TB>>>(p_mol,  mol2rxn, p_feat, NM, 128, 64);

    // ===== MLP head =====
    fc1_kernel<<<dim3(NB / 16, 4), 128>>>(p_feat, w_fc1, b_fc1, prelu, p_hid);
    fc2_kernel<<<dim3(NB / 16, 6), 128>>>(p_hid, w_fc2, b_fc2, out);
}

// round 5
// speedup vs baseline: 2.6761x; 1.0743x over previous
#include <cuda_runtime.h>
#include <cuda_fp16.h>
#include <math.h>
#include <stdint.h>

// ---------------- problem constants ----------------
#define NN      100000
#define NE      800000
#define DD      64
#define RM      8
#define NM      5000
#define NRE     40000
#define RR      4
#define NB      1024
#define DH      512
#define DO      703

// ---------------- scratch ----------------
__device__ __half g_hW [(size_t)RM * NN * DD];   // 102.4 MB (fp16)
__device__ float g_h1 [(size_t)NN * DD];
__device__ float g_h2 [(size_t)NN * DD];
__device__ float g_atts[(size_t)RM * NN];
__device__ float g_attd[(size_t)RM * NN];
__device__ float g_sum [NN];
__device__ float g_B   [16 * 64];
__device__ float g_mol [(size_t)NM * DD];
__device__ float g_molr[(size_t)NM * DD];
__device__ float g_feat[(size_t)NB * 2 * DD];
__device__ float g_hid [(size_t)NB * DH];

__device__ __forceinline__ void red_add_v4(float* p, float4 v) {
    asm volatile("red.global.add.v4.f32 [%0], {%1,%2,%3,%4};"
                 :: "l"(p), "f"(v.x), "f"(v.y), "f"(v.z), "f"(v.w) : "memory");
}

__global__ void fill_kernel(float* __restrict__ p, float v, int n) {
    int i = blockIdx.x * blockDim.x + threadIdx.x;
    if (i < n) p[i] = v;
}
__global__ void fill4_kernel(float4* __restrict__ p, int n4) {
    int i = blockIdx.x * blockDim.x + threadIdx.x;
    if (i < n4) p[i] = make_float4(0.f, 0.f, 0.f, 0.f);
}

// ---------------- b[r] = W_r @ a_r precompute ----------------
__global__ void prep_b_kernel(const float* __restrict__ W,
                              const float* __restrict__ a_src,
                              const float* __restrict__ a_dst,
                              float* __restrict__ B, int R)
{
    int r = blockIdx.x, d = threadIdx.x;   // 64 threads
    __shared__ float as[64], ad[64];
    as[d] = a_src[r * 64 + d];
    ad[d] = a_dst[r * 64 + d];
    __syncthreads();
    const float* Wr = W + (size_t)r * 4096 + d * 64;
    float s1 = 0.f, s2 = 0.f;
    #pragma unroll 8
    for (int e = 0; e < 64; e++) {
        float w = Wr[e];
        s1 += w * as[e];
        s2 += w * ad[e];
    }
    B[r * 64 + d]       = s1;
    B[(R + r) * 64 + d] = s2;
}

// ---------------- attention logits: att[r,n] = h[n] . B[r] ----------------
template<int R>
__global__ void att_kernel(const float* __restrict__ h, const float* __restrict__ B,
                           float* __restrict__ att_s, float* __restrict__ att_d, int N)
{
    __shared__ float Bs[2 * R * 64];
    const int tid = threadIdx.x;   // 128
    for (int i = tid; i < 2 * R * 64; i += 128) Bs[i] = B[i];
    __syncthreads();
    int n = blockIdx.x * 128 + tid;
    if (n >= N) return;
    float acc[2 * R];
    #pragma unroll
    for (int rr = 0; rr < 2 * R; rr++) acc[rr] = 0.f;
    const float4* hp = (const float4*)&h[(size_t)n * 64];
    #pragma unroll
    for (int d4 = 0; d4 < 16; d4++) {
        float4 hv = hp[d4];
        #pragma unroll
        for (int rr = 0; rr < 2 * R; rr++) {
            float4 b = *(const float4*)&Bs[rr * 64 + d4 * 4];
            acc[rr] += hv.x * b.x + hv.y * b.y + hv.z * b.z + hv.w * b.w;
        }
    }
    #pragma unroll
    for (int r = 0; r < R; r++) {
        att_s[(size_t)r * N + n] = acc[r];
        att_d[(size_t)r * N + n] = acc[R + r];
    }
}

// ---------------- hW GEMM (FFMA2, 8x8 tile, fp16 output) ----------------
#define HS_STRIDE 66
#define WT_STRIDE 66

__global__ __launch_bounds__(128, 2)
void hw_gemm_kernel(const float* __restrict__ h,
                    const float* __restrict__ W,
                    __half* __restrict__ hW,
                    int N, int R)
{
    __shared__ float hs[128 * HS_STRIDE];
    __shared__ float Wt[64 * WT_STRIDE];

    const int tid = threadIdx.x;
    const int n0  = blockIdx.x * 128;
    const int ng  = tid >> 3;   // 0..15
    const int cg  = tid & 7;    // 0..7

    #pragma unroll
    for (int it = 0; it < 16; it++) {
        int idx4 = it * 128 + tid;
        int row  = idx4 >> 4;
        int col  = (idx4 & 15) * 4;
        int n    = n0 + row;
        float4 v = make_float4(0.f, 0.f, 0.f, 0.f);
        if (n < N) v = *(const float4*)&h[(size_t)n * 64 + col];
        float* d = &hs[row * HS_STRIDE + col];
        d[0] = v.x; d[1] = v.y; d[2] = v.z; d[3] = v.w;
    }

    for (int r = 0; r < R; r++) {
        __syncthreads();
        const float* Wr = W + (size_t)r * 4096;
        #pragma unroll
        for (int it = 0; it < 8; it++) {
            int idx4 = it * 128 + tid;
            int k    = idx4 >> 4;
            int c    = (idx4 & 15) * 4;
            float4 v = *(const float4*)&Wr[k * 64 + c];
            Wt[(((c + 0) & 7) * 8 + ((c + 0) >> 3)) * WT_STRIDE + k] = v.x;
            Wt[(((c + 1) & 7) * 8 + ((c + 1) >> 3)) * WT_STRIDE + k] = v.y;
            Wt[(((c + 2) & 7) * 8 + ((c + 2) >> 3)) * WT_STRIDE + k] = v.z;
            Wt[(((c + 3) & 7) * 8 + ((c + 3) >> 3)) * WT_STRIDE + k] = v.w;
        }
        __syncthreads();

        unsigned long long acc[8][8];
        #pragma unroll
        for (int i = 0; i < 8; i++)
            #pragma unroll
            for (int j = 0; j < 8; j++) acc[i][j] = 0ULL;

        #pragma unroll 2
        for (int kp = 0; kp < 32; kp++) {
            const int k = kp * 2;
            unsigned long long hv[8], wv[8];
            #pragma unroll
            for (int i = 0; i < 8; i++)
                hv[i] = *(const unsigned long long*)&hs[(i * 16 + ng) * HS_STRIDE + k];
            #pragma unroll
            for (int j = 0; j < 8; j++)
                wv[j] = *(const unsigned long long*)&Wt[(j * 8 + cg) * WT_STRIDE + k];
            #pragma unroll
            for (int i = 0; i < 8; i++)
                #pragma unroll
                for (int j = 0; j < 8; j++)
                    asm("fma.rn.f32x2 %0, %1, %2, %0;"
                        : "+l"(acc[i][j]) : "l"(hv[i]), "l"(wv[j]));
        }

        // epilogue: 8 fp32 sums -> 4 half2 -> one STG.128 per node
        #pragma unroll
        for (int i = 0; i < 8; i++) {
            int n = n0 + i * 16 + ng;
            if (n < N) {
                float v[8];
                #pragma unroll
                for (int j = 0; j < 8; j++) {
                    float2 p = *(float2*)&acc[i][j];
                    v[j] = p.x + p.y;
                }
                __half2 hv4[4];
                #pragma unroll
                for (int j = 0; j < 4; j++)
                    hv4[j] = __floats2half2_rn(v[2 * j], v[2 * j + 1]);
                *(uint4*)&hW[((size_t)r * N + n) * 64 + cg * 8] = *(uint4*)hv4;
            }
        }
    }
}

// ---------------- fused edge pass: agg += exp(score)*hW, dsum += exp(score) ----------------
// 8 threads per edge; each reads 16B (8 halves) of the fp16 hW row.
__global__ void edge_fused_kernel(const int* __restrict__ src, const int* __restrict__ dst,
                                  const int* __restrict__ rel,
                                  const float* __restrict__ att_s, const float* __restrict__ att_d,
                                  const __half* __restrict__ hW,
                                  float* __restrict__ dsum, float* __restrict__ agg,
                                  int E, int N)
{
    int t = blockIdx.x * blockDim.x + threadIdx.x;
    int e = t >> 3;
    if (e >= E) return;
    int g = t & 7;
    int s = src[e], d = dst[e], r = rel[e];
    float v = att_s[(size_t)r * N + s] + att_d[(size_t)r * N + d];
    v = (v > 0.f) ? v : 0.2f * v;
    float x = __expf(v);

    uint4 raw = *(const uint4*)&hW[((size_t)r * N + s) * 64 + g * 8];
    __half2* hp = (__half2*)&raw;
    float2 f0 = __half22float2(hp[0]);
    float2 f1 = __half22float2(hp[1]);
    float2 f2 = __half22float2(hp[2]);
    float2 f3 = __half22float2(hp[3]);

    float* base = &agg[(size_t)d * 64 + g * 8];
    red_add_v4(base,     make_float4(x * f0.x, x * f0.y, x * f1.x, x * f1.y));
    red_add_v4(base + 4, make_float4(x * f2.x, x * f2.y, x * f3.x, x * f3.y));
    if (g == 0) atomicAdd(&dsum[d], x);
}

// ---------------- normalize by dsum + ELU (in place) ----------------
__global__ void norm_elu_kernel(float* __restrict__ agg, const float* __restrict__ dsum, int total) {
    int i = blockIdx.x * blockDim.x + threadIdx.x;
    if (i >= total) return;
    float s = dsum[i >> 6];
    float v = agg[i] / (s + 1e-9f);
    agg[i] = (v > 0.f) ? v : expm1f(v);
}

__global__ void segsum_kernel(const float* __restrict__ x, const int* __restrict__ seg,
                              float* __restrict__ out, int n, int ostride, int ooff)
{
    int t = blockIdx.x * blockDim.x + threadIdx.x;
    int i = t >> 4;
    if (i >= n) return;
    int g = (t & 15) * 4;
    int s = seg[i];
    float4 v = *(const float4*)&x[(size_t)i * 64 + g];
    red_add_v4(&out[(size_t)s * ostride + ooff + g], v);
}

// ---------------- MLP head ----------------
__global__ void fc1_kernel(const float* __restrict__ feat, const float* __restrict__ w,
                           const float* __restrict__ b, const float* __restrict__ prelu,
                           float* __restrict__ out)
{
    const int r0 = blockIdx.x * 16;
    const int c0 = blockIdx.y * 128;
    __shared__ float fs[16][128];
    #pragma unroll
    for (int it = 0; it < 4; it++) {
        int idx4 = it * 128 + threadIdx.x;
        int row = idx4 >> 5, col = (idx4 & 31) * 4;
        *(float4*)&fs[row][col] = *(const float4*)&feat[(size_t)(r0 + row) * 128 + col];
    }
    __syncthreads();
    const int col = c0 + threadIdx.x;
    float acc[16];
    #pragma unroll
    for (int j = 0; j < 16; j++) acc[j] = 0.f;
    #pragma unroll 4
    for (int k = 0; k < 128; k++) {
        float wv = w[k * 512 + col];
        #pragma unroll
        for (int j = 0; j < 16; j++) acc[j] += fs[j][k] * wv;
    }
    float bb = b[col], p = prelu[0];
    #pragma unroll
    for (int j = 0; j < 16; j++) {
        float v = acc[j] + bb;
        out[(size_t)(r0 + j) * 512 + col] = (v > 0.f) ? v : p * v;
    }
}

__global__ void fc2_kernel(const float* __restrict__ hid, const float* __restrict__ w,
                           const float* __restrict__ b, float* __restrict__ out)
{
    const int r0 = blockIdx.x * 16;
    const int c0 = blockIdx.y * 128;
    __shared__ float hs[16][512];
    #pragma unroll
    for (int it = 0; it < 16; it++) {
        int idx4 = it * 128 + threadIdx.x;
        int row = idx4 >> 7, col = (idx4 & 127) * 4;
        *(float4*)&hs[row][col] = *(const float4*)&hid[(size_t)(r0 + row) * 512 + col];
    }
    __syncthreads();
    const int col = c0 + threadIdx.x;
    if (col >= DO) return;
    float acc[16];
    #pragma unroll
    for (int j = 0; j < 16; j++) acc[j] = 0.f;
    #pragma unroll 4
    for (int k = 0; k < 512; k++) {
        float wv = w[k * DO + col];
        #pragma unroll
        for (int j = 0; j < 16; j++) acc[j] += hs[j][k] * wv;
    }
    float bb = b[col];
    #pragma unroll
    for (int j = 0; j < 16; j++)
        out[(size_t)(r0 + j) * DO + col] = acc[j] + bb;
}

// ---------------- launch ----------------
static inline int cdiv(int a, int b) { return (a + b - 1) / b; }

extern "C" void kernel_launch(void* const* d_in, const int* in_sizes, int n_in,
                              void* d_out, int out_size)
{
    const float* node_feats = (const float*)d_in[0];
    const int*   edge_src   = (const int*)  d_in[1];
    const int*   edge_dst   = (const int*)  d_in[2];
    const int*   edge_rel   = (const int*)  d_in[3];
    const int*   node2mol   = (const int*)  d_in[4];
    const int*   rxn_src    = (const int*)  d_in[5];
    const int*   rxn_dst    = (const int*)  d_in[6];
    const int*   rxn_rel    = (const int*)  d_in[7];
    const int*   mol2rxn    = (const int*)  d_in[8];
    const float* W1    = (const float*)d_in[9];
    const float* as1   = (const float*)d_in[10];
    const float* ad1   = (const float*)d_in[11];
    const float* W2    = (const float*)d_in[12];
    const float* as2   = (const float*)d_in[13];
    const float* ad2   = (const float*)d_in[14];
    const float* Wr    = (const float*)d_in[15];
    const float* asr   = (const float*)d_in[16];
    const float* adr   = (const float*)d_in[17];
    const float* w_fc1 = (const float*)d_in[18];
    const float* b_fc1 = (const float*)d_in[19];
    const float* prelu = (const float*)d_in[20];
    const float* w_fc2 = (const float*)d_in[21];
    const float* b_fc2 = (const float*)d_in[22];
    float* out = (float*)d_out;

    __half* p_hW;
    float *p_h1, *p_h2, *p_atts, *p_attd, *p_sum, *p_B,
          *p_mol, *p_molr, *p_feat, *p_hid;
    cudaGetSymbolAddress((void**)&p_hW,   g_hW);
    cudaGetSymbolAddress((void**)&p_h1,   g_h1);
    cudaGetSymbolAddress((void**)&p_h2,   g_h2);
    cudaGetSymbolAddress((void**)&p_atts, g_atts);
    cudaGetSymbolAddress((void**)&p_attd, g_attd);
    cudaGetSymbolAddress((void**)&p_sum,  g_sum);
    cudaGetSymbolAddress((void**)&p_B,    g_B);
    cudaGetSymbolAddress((void**)&p_mol,  g_mol);
    cudaGetSymbolAddress((void**)&p_molr, g_molr);
    cudaGetSymbolAddress((void**)&p_feat, g_feat);
    cudaGetSymbolAddress((void**)&p_hid,  g_hid);

    const int TB = 256;

    // ===== atom layer 1 =====
    fill_kernel<<<cdiv(NN, TB), TB>>>(p_sum, 0.f, NN);
    fill4_kernel<<<cdiv(NN * 16, TB), TB>>>((float4*)p_h1, NN * 16);
    prep_b_kernel<<<RM, 64>>>(W1, as1, ad1, p_B, RM);
    att_kernel<RM><<<cdiv(NN, 128), 128>>>(node_feats, p_B, p_atts, p_attd, NN);
    hw_gemm_kernel<<<cdiv(NN, 128), 128>>>(node_feats, W1, p_hW, NN, RM);
    edge_fused_kernel<<<cdiv(NE * 8, TB), TB>>>(edge_src, edge_dst, edge_rel,
                                                p_atts, p_attd, p_hW, p_sum, p_h1, NE, NN);
    norm_elu_kernel<<<cdiv(NN * DD, TB), TB>>>(p_h1, p_sum, NN * DD);

    // ===== atom layer 2 =====
    fill_kernel<<<cdiv(NN, TB), TB>>>(p_sum, 0.f, NN);
    fill4_kernel<<<cdiv(NN * 16, TB), TB>>>((float4*)p_h2, NN * 16);
    prep_b_kernel<<<RM, 64>>>(W2, as2, ad2, p_B, RM);
    att_kernel<RM><<<cdiv(NN, 128), 128>>>(p_h1, p_B, p_atts, p_attd, NN);
    hw_gemm_kernel<<<cdiv(NN, 128), 128>>>(p_h1, W2, p_hW, NN, RM);
    edge_fused_kernel<<<cdiv(NE * 8, TB), TB>>>(edge_src, edge_dst, edge_rel,
                                                p_atts, p_attd, p_hW, p_sum, p_h2, NE, NN);
    norm_elu_kernel<<<cdiv(NN * DD, TB), TB>>>(p_h2, p_sum, NN * DD);

    // ===== molecule readout =====
    fill4_kernel<<<cdiv(NM * 16, TB), TB>>>((float4*)p_mol, NM * 16);
    segsum_kernel<<<cdiv(NN * 16, TB), TB>>>(p_h2, node2mol, p_mol, NN, 64, 0);

    // ===== reaction-level RGAT =====
    fill_kernel<<<cdiv(NM, TB), TB>>>(p_sum, 0.f, NM);
    fill4_kernel<<<cdiv(NM * 16, TB), TB>>>((float4*)p_molr, NM * 16);
    prep_b_kernel<<<RR, 64>>>(Wr, asr, adr, p_B, RR);
    att_kernel<RR><<<cdiv(NM, 128), 128>>>(p_mol, p_B, p_atts, p_attd, NM);
    hw_gemm_kernel<<<cdiv(NM, 128), 128>>>(p_mol, Wr, p_hW, NM, RR);
    edge_fused_kernel<<<cdiv(NRE * 8, TB), TB>>>(rxn_src, rxn_dst, rxn_rel,
                                                 p_atts, p_attd, p_hW, p_sum, p_molr, NRE, NM);
    norm_elu_kernel<<<cdiv(NM * DD, TB), TB>>>(p_molr, p_sum, NM * DD);

    // ===== reaction readout =====
    fill4_kernel<<<cdiv(NB * 32, TB), TB>>>((float4*)p_feat, NB * 32);
    segsum_kernel<<<cdiv(NM * 16, TB), TB>>>(p_molr, mol2rxn, p_feat, NM, 128, 0);
    segsum_kernel<<<cdiv(NM * 16, TB), TB>>>(p_mol,  mol2rxn, p_feat, NM, 128, 64);

    // ===== MLP head =====
    fc1_kernel<<<dim3(NB / 16, 4), 128>>>(p_feat, w_fc1, b_fc1, prelu, p_hid);
    fc2_kernel<<<dim3(NB / 16, 6), 128>>>(p_hid, w_fc2, b_fc2, out);
}

// round 7
// speedup vs baseline: 3.5940x; 1.3430x over previous
#include <cuda_runtime.h>
#include <cuda_fp16.h>
#include <math.h>
#include <stdint.h>

// ---------------- problem constants ----------------
#define NN      100000
#define NE      800000
#define DD      64
#define RM      8
#define NM      5000
#define NRE     40000
#define RR      4
#define NB      1024
#define DH      512
#define DO      703

// ---------------- scratch ----------------
__device__ __half g_hW [(size_t)RM * NN * DD];   // 102.4 MB (fp16)
__device__ float g_h1 [(size_t)NN * DD];
__device__ float g_h2 [(size_t)NN * DD];
__device__ float g_atts[(size_t)RM * NN];
__device__ float g_attd[(size_t)RM * NN];
__device__ float g_sum [NN];
__device__ float g_B   [16 * 64];
__device__ float g_mol [(size_t)NM * DD];
__device__ float g_molr[(size_t)NM * DD];
__device__ float g_feat[(size_t)NB * 2 * DD];
__device__ float g_hid [(size_t)NB * DH];

__device__ __forceinline__ void red_add_v4(float* p, float4 v) {
    asm volatile("red.global.add.v4.f32 [%0], {%1,%2,%3,%4};"
                 :: "l"(p), "f"(v.x), "f"(v.y), "f"(v.z), "f"(v.w) : "memory");
}

__global__ void fill_kernel(float* __restrict__ p, float v, int n) {
    int i = blockIdx.x * blockDim.x + threadIdx.x;
    if (i < n) p[i] = v;
}
__global__ void fill4_kernel(float4* __restrict__ p, int n4) {
    int i = blockIdx.x * blockDim.x + threadIdx.x;
    if (i < n4) p[i] = make_float4(0.f, 0.f, 0.f, 0.f);
}

// ---------------- b[r] = W_r @ a_r precompute ----------------
__global__ void prep_b_kernel(const float* __restrict__ W,
                              const float* __restrict__ a_src,
                              const float* __restrict__ a_dst,
                              float* __restrict__ B, int R)
{
    int r = blockIdx.x, d = threadIdx.x;   // 64 threads
    __shared__ float as[64], ad[64];
    as[d] = a_src[r * 64 + d];
    ad[d] = a_dst[r * 64 + d];
    __syncthreads();
    const float* Wr = W + (size_t)r * 4096 + d * 64;
    float s1 = 0.f, s2 = 0.f;
    #pragma unroll 8
    for (int e = 0; e < 64; e++) {
        float w = Wr[e];
        s1 += w * as[e];
        s2 += w * ad[e];
    }
    B[r * 64 + d]       = s1;
    B[(R + r) * 64 + d] = s2;
}

// ---------------- attention logits: att[r,n] = h[n] . B[r] ----------------
template<int R>
__global__ void att_kernel(const float* __restrict__ h, const float* __restrict__ B,
                           float* __restrict__ att_s, float* __restrict__ att_d, int N)
{
    __shared__ float Bs[2 * R * 64];
    const int tid = threadIdx.x;   // 128
    for (int i = tid; i < 2 * R * 64; i += 128) Bs[i] = B[i];
    __syncthreads();
    int n = blockIdx.x * 128 + tid;
    if (n >= N) return;
    float acc[2 * R];
    #pragma unroll
    for (int rr = 0; rr < 2 * R; rr++) acc[rr] = 0.f;
    const float4* hp = (const float4*)&h[(size_t)n * 64];
    #pragma unroll
    for (int d4 = 0; d4 < 16; d4++) {
        float4 hv = hp[d4];
        #pragma unroll
        for (int rr = 0; rr < 2 * R; rr++) {
            float4 b = *(const float4*)&Bs[rr * 64 + d4 * 4];
            acc[rr] += hv.x * b.x + hv.y * b.y + hv.z * b.z + hv.w * b.w;
        }
    }
    #pragma unroll
    for (int r = 0; r < R; r++) {
        att_s[(size_t)r * N + n] = acc[r];
        att_d[(size_t)r * N + n] = acc[R + r];
    }
}

// ================= warp-MMA helpers (sm_80 baseline, compile in compute_103) =================
__device__ __forceinline__ uint32_t smem_u32(const void* p) {
    return (uint32_t)__cvta_generic_to_shared(p);
}

#define LDSM_X4(r0, r1, r2, r3, addr) \
    asm volatile("ldmatrix.sync.aligned.m8n8.x4.shared.b16 {%0,%1,%2,%3}, [%4];" \
                 : "=r"(r0), "=r"(r1), "=r"(r2), "=r"(r3) : "r"(addr))

#define LDSM_X2T(r0, r1, addr) \
    asm volatile("ldmatrix.sync.aligned.m8n8.x2.trans.shared.b16 {%0,%1}, [%2];" \
                 : "=r"(r0), "=r"(r1) : "r"(addr))

#define MMA16816(c, a, b) \
    asm volatile("mma.sync.aligned.m16n8k16.row.col.f32.f16.f16.f32 " \
                 "{%0,%1,%2,%3}, {%4,%5,%6,%7}, {%8,%9}, {%0,%1,%2,%3};" \
                 : "+f"((c)[0]), "+f"((c)[1]), "+f"((c)[2]), "+f"((c)[3]) \
                 : "r"((a)[0]), "r"((a)[1]), "r"((a)[2]), "r"((a)[3]), \
                   "r"((b)[0]), "r"((b)[1]))

// ---------------- hW GEMM on HMMA tensor cores ----------------
// CTA: 128 threads / 4 warps, 128-node tile. Warp w owns rows [w*32, w*32+32).
// A fragments (h tile, fp16) loaded once via ldmatrix.x4 and reused for all R.
// W stored row-major [k][c] fp16 (stride 72 halves) -> B frags via ldmatrix.x2.trans.
// Epilogue stages fp16 rows in smem, then coalesced STG.128 to hW.
__global__ __launch_bounds__(128)
void hw_mma_kernel(const float* __restrict__ h,
                   const float* __restrict__ W,
                   __half* __restrict__ hW,
                   int N, int R)
{
    __shared__ __align__(16) __half sa [128 * 72];  // 18 KB  h tile
    __shared__ __align__(16) __half swt[64 * 72];   // 9 KB   W_r tile [k][c]
    __shared__ __align__(16) __half sc [128 * 72];  // 18 KB  output staging

    const int tid  = threadIdx.x;
    const int wid  = tid >> 5;
    const int lane = tid & 31;
    const int n0   = blockIdx.x * 128;

    // ---- h tile: fp32 -> fp16, padded stride 72 (ldmatrix conflict-free) ----
    #pragma unroll
    for (int it = 0; it < 8; it++) {
        int chunk = it * 128 + tid;        // 0..1023 = 128 rows x 8 chunks
        int row = chunk >> 3;
        int c8  = (chunk & 7) * 8;
        int n = n0 + row;
        float4 a = make_float4(0.f,0.f,0.f,0.f), b = a;
        if (n < N) {
            a = *(const float4*)&h[(size_t)n * 64 + c8];
            b = *(const float4*)&h[(size_t)n * 64 + c8 + 4];
        }
        __half2 pk[4];
        pk[0] = __floats2half2_rn(a.x, a.y);
        pk[1] = __floats2half2_rn(a.z, a.w);
        pk[2] = __floats2half2_rn(b.x, b.y);
        pk[3] = __floats2half2_rn(b.z, b.w);
        *(uint4*)&sa[row * 72 + c8] = *(uint4*)pk;
    }
    __syncthreads();

    // ---- A fragments: 2 m-tiles x 4 k-tiles, held across all relations ----
    uint32_t afrag[2][4][4];
    {
        const int l15 = lane & 15;
        const int lhi = lane >> 4;
        #pragma unroll
        for (int mt = 0; mt < 2; mt++)
            #pragma unroll
            for (int kk = 0; kk < 4; kk++) {
                uint32_t addr = smem_u32(&sa[(wid * 32 + mt * 16 + l15) * 72 + kk * 16 + lhi * 8]);
                LDSM_X4(afrag[mt][kk][0], afrag[mt][kk][1],
                        afrag[mt][kk][2], afrag[mt][kk][3], addr);
            }
    }

    for (int r = 0; r < R; r++) {
        __syncthreads();   // swt free (prev B-ldmatrix done), sc free (prev stores done)
        const float* Wr = W + (size_t)r * 4096;
        for (int i = tid; i < 4096; i += 128)
            swt[(i >> 6) * 72 + (i & 63)] = __float2half(Wr[i]);
        __syncthreads();

        float c[2][8][4];
        #pragma unroll
        for (int mt = 0; mt < 2; mt++)
            #pragma unroll
            for (int j = 0; j < 8; j++)
                #pragma unroll
                for (int q = 0; q < 4; q++) c[mt][j][q] = 0.f;

        #pragma unroll
        for (int kk = 0; kk < 4; kk++) {
            uint32_t b[8][2];
            const int l15 = lane & 15;
            #pragma unroll
            for (int j = 0; j < 8; j++) {
                uint32_t addr = smem_u32(&swt[(kk * 16 + l15) * 72 + j * 8]);
                LDSM_X2T(b[j][0], b[j][1], addr);
            }
            #pragma unroll
            for (int mt = 0; mt < 2; mt++)
                #pragma unroll
                for (int j = 0; j < 8; j++)
                    MMA16816(c[mt][j], afrag[mt][kk], b[j]);
        }

        // ---- stage fragments to sc (fp16) ----
        {
            const int t4 = lane >> 2;
            const int t2 = (lane & 3) * 2;
            #pragma unroll
            for (int mt = 0; mt < 2; mt++) {
                int rr = wid * 32 + mt * 16 + t4;
                #pragma unroll
                for (int j = 0; j < 8; j++) {
                    *(__half2*)&sc[rr * 72 + j * 8 + t2]       = __floats2half2_rn(c[mt][j][0], c[mt][j][1]);
                    *(__half2*)&sc[(rr + 8) * 72 + j * 8 + t2] = __floats2half2_rn(c[mt][j][2], c[mt][j][3]);
                }
            }
        }
        __syncthreads();

        // ---- coalesced store: each row = 128B contiguous ----
        #pragma unroll
        for (int it = 0; it < 8; it++) {
            int idx = it * 128 + tid;
            int row = idx >> 3;
            int q   = idx & 7;
            int n = n0 + row;
            if (n < N)
                *(uint4*)&hW[((size_t)r * N + n) * 64 + q * 8] = *(uint4*)&sc[row * 72 + q * 8];
        }
    }
}

// ---------------- fused edge pass ----------------
__global__ void edge_fused_kernel(const int* __restrict__ src, const int* __restrict__ dst,
                                  const int* __restrict__ rel,
                                  const float* __restrict__ att_s, const float* __restrict__ att_d,
                                  const __half* __restrict__ hW,
                                  float* __restrict__ dsum, float* __restrict__ agg,
                                  int E, int N)
{
    int t = blockIdx.x * blockDim.x + threadIdx.x;
    int e = t >> 3;
    if (e >= E) return;
    int g = t & 7;
    int s = src[e], d = dst[e], r = rel[e];
    float v = att_s[(size_t)r * N + s] + att_d[(size_t)r * N + d];
    v = (v > 0.f) ? v : 0.2f * v;
    float x = __expf(v);

    uint4 raw = *(const uint4*)&hW[((size_t)r * N + s) * 64 + g * 8];
    __half2* hp = (__half2*)&raw;
    float2 f0 = __half22float2(hp[0]);
    float2 f1 = __half22float2(hp[1]);
    float2 f2 = __half22float2(hp[2]);
    float2 f3 = __half22float2(hp[3]);

    float* base = &agg[(size_t)d * 64 + g * 8];
    red_add_v4(base,     make_float4(x * f0.x, x * f0.y, x * f1.x, x * f1.y));
    red_add_v4(base + 4, make_float4(x * f2.x, x * f2.y, x * f3.x, x * f3.y));
    if (g == 0) atomicAdd(&dsum[d], x);
}

__global__ void norm_elu_kernel(float* __restrict__ agg, const float* __restrict__ dsum, int total) {
    int i = blockIdx.x * blockDim.x + threadIdx.x;
    if (i >= total) return;
    float s = dsum[i >> 6];
    float v = agg[i] / (s + 1e-9f);
    agg[i] = (v > 0.f) ? v : expm1f(v);
}

__global__ void segsum_kernel(const float* __restrict__ x, const int* __restrict__ seg,
                              float* __restrict__ out, int n, int ostride, int ooff)
{
    int t = blockIdx.x * blockDim.x + threadIdx.x;
    int i = t >> 4;
    if (i >= n) return;
    int g = (t & 15) * 4;
    int s = seg[i];
    float4 v = *(const float4*)&x[(size_t)i * 64 + g];
    red_add_v4(&out[(size_t)s * ostride + ooff + g], v);
}

// ---------------- MLP head ----------------
__global__ void fc1_kernel(const float* __restrict__ feat, const float* __restrict__ w,
                           const float* __restrict__ b, const float* __restrict__ prelu,
                           float* __restrict__ out)
{
    const int r0 = blockIdx.x * 16;
    const int c0 = blockIdx.y * 128;
    __shared__ float fs[16][128];
    #pragma unroll
    for (int it = 0; it < 4; it++) {
        int idx4 = it * 128 + threadIdx.x;
        int row = idx4 >> 5, col = (idx4 & 31) * 4;
        *(float4*)&fs[row][col] = *(const float4*)&feat[(size_t)(r0 + row) * 128 + col];
    }
    __syncthreads();
    const int col = c0 + threadIdx.x;
    float acc[16];
    #pragma unroll
    for (int j = 0; j < 16; j++) acc[j] = 0.f;
    #pragma unroll 4
    for (int k = 0; k < 128; k++) {
        float wv = w[k * 512 + col];
        #pragma unroll
        for (int j = 0; j < 16; j++) acc[j] += fs[j][k] * wv;
    }
    float bb = b[col], p = prelu[0];
    #pragma unroll
    for (int j = 0; j < 16; j++) {
        float v = acc[j] + bb;
        out[(size_t)(r0 + j) * 512 + col] = (v > 0.f) ? v : p * v;
    }
}

__global__ void fc2_kernel(const float* __restrict__ hid, const float* __restrict__ w,
                           const float* __restrict__ b, float* __restrict__ out)
{
    const int r0 = blockIdx.x * 16;
    const int c0 = blockIdx.y * 128;
    __shared__ float hs[16][512];
    #pragma unroll
    for (int it = 0; it < 16; it++) {
        int idx4 = it * 128 + threadIdx.x;
        int row = idx4 >> 7, col = (idx4 & 127) * 4;
        *(float4*)&hs[row][col] = *(const float4*)&hid[(size_t)(r0 + row) * 512 + col];
    }
    __syncthreads();
    const int col = c0 + threadIdx.x;
    if (col >= DO) return;
    float acc[16];
    #pragma unroll
    for (int j = 0; j < 16; j++) acc[j] = 0.f;
    #pragma unroll 4
    for (int k = 0; k < 512; k++) {
        float wv = w[k * DO + col];
        #pragma unroll
        for (int j = 0; j < 16; j++) acc[j] += hs[j][k] * wv;
    }
    float bb = b[col];
    #pragma unroll
    for (int j = 0; j < 16; j++)
        out[(size_t)(r0 + j) * DO + col] = acc[j] + bb;
}

// ---------------- launch ----------------
static inline int cdiv(int a, int b) { return (a + b - 1) / b; }

extern "C" void kernel_launch(void* const* d_in, const int* in_sizes, int n_in,
                              void* d_out, int out_size)
{
    const float* node_feats = (const float*)d_in[0];
    const int*   edge_src   = (const int*)  d_in[1];
    const int*   edge_dst   = (const int*)  d_in[2];
    const int*   edge_rel   = (const int*)  d_in[3];
    const int*   node2mol   = (const int*)  d_in[4];
    const int*   rxn_src    = (const int*)  d_in[5];
    const int*   rxn_dst    = (const int*)  d_in[6];
    const int*   rxn_rel    = (const int*)  d_in[7];
    const int*   mol2rxn    = (const int*)  d_in[8];
    const float* W1    = (const float*)d_in[9];
    const float* as1   = (const float*)d_in[10];
    const float* ad1   = (const float*)d_in[11];
    const float* W2    = (const float*)d_in[12];
    const float* as2   = (const float*)d_in[13];
    const float* ad2   = (const float*)d_in[14];
    const float* Wr    = (const float*)d_in[15];
    const float* asr   = (const float*)d_in[16];
    const float* adr   = (const float*)d_in[17];
    const float* w_fc1 = (const float*)d_in[18];
    const float* b_fc1 = (const float*)d_in[19];
    const float* prelu = (const float*)d_in[20];
    const float* w_fc2 = (const float*)d_in[21];
    const float* b_fc2 = (const float*)d_in[22];
    float* out = (float*)d_out;

    __half* p_hW;
    float *p_h1, *p_h2, *p_atts, *p_attd, *p_sum, *p_B,
          *p_mol, *p_molr, *p_feat, *p_hid;
    cudaGetSymbolAddress((void**)&p_hW,   g_hW);
    cudaGetSymbolAddress((void**)&p_h1,   g_h1);
    cudaGetSymbolAddress((void**)&p_h2,   g_h2);
    cudaGetSymbolAddress((void**)&p_atts, g_atts);
    cudaGetSymbolAddress((void**)&p_attd, g_attd);
    cudaGetSymbolAddress((void**)&p_sum,  g_sum);
    cudaGetSymbolAddress((void**)&p_B,    g_B);
    cudaGetSymbolAddress((void**)&p_mol,  g_mol);
    cudaGetSymbolAddress((void**)&p_molr, g_molr);
    cudaGetSymbolAddress((void**)&p_feat, g_feat);
    cudaGetSymbolAddress((void**)&p_hid,  g_hid);

    const int TB = 256;

    // ===== atom layer 1 =====
    fill_kernel<<<cdiv(NN, TB), TB>>>(p_sum, 0.f, NN);
    fill4_kernel<<<cdiv(NN * 16, TB), TB>>>((float4*)p_h1, NN * 16);
    prep_b_kernel<<<RM, 64>>>(W1, as1, ad1, p_B, RM);
    att_kernel<RM><<<cdiv(NN, 128), 128>>>(node_feats, p_B, p_atts, p_attd, NN);
    hw_mma_kernel<<<cdiv(NN, 128), 128>>>(node_feats, W1, p_hW, NN, RM);
    edge_fused_kernel<<<cdiv(NE * 8, TB), TB>>>(edge_src, edge_dst, edge_rel,
                                                p_atts, p_attd, p_hW, p_sum, p_h1, NE, NN);
    norm_elu_kernel<<<cdiv(NN * DD, TB), TB>>>(p_h1, p_sum, NN * DD);

    // ===== atom layer 2 =====
    fill_kernel<<<cdiv(NN, TB), TB>>>(p_sum, 0.f, NN);
    fill4_kernel<<<cdiv(NN * 16, TB), TB>>>((float4*)p_h2, NN * 16);
    prep_b_kernel<<<RM, 64>>>(W2, as2, ad2, p_B, RM);
    att_kernel<RM><<<cdiv(NN, 128), 128>>>(p_h1, p_B, p_atts, p_attd, NN);
    hw_mma_kernel<<<cdiv(NN, 128), 128>>>(p_h1, W2, p_hW, NN, RM);
    edge_fused_kernel<<<cdiv(NE * 8, TB), TB>>>(edge_src, edge_dst, edge_rel,
                                                p_atts, p_attd, p_hW, p_sum, p_h2, NE, NN);
    norm_elu_kernel<<<cdiv(NN * DD, TB), TB>>>(p_h2, p_sum, NN * DD);

    // ===== molecule readout =====
    fill4_kernel<<<cdiv(NM * 16, TB), TB>>>((float4*)p_mol, NM * 16);
    segsum_kernel<<<cdiv(NN * 16, TB), TB>>>(p_h2, node2mol, p_mol, NN, 64, 0);

    // ===== reaction-level RGAT =====
    fill_kernel<<<cdiv(NM, TB), TB>>>(p_sum, 0.f, NM);
    fill4_kernel<<<cdiv(NM * 16, TB), TB>>>((float4*)p_molr, NM * 16);
    prep_b_kernel<<<RR, 64>>>(Wr, asr, adr, p_B, RR);
    att_kernel<RR><<<cdiv(NM, 128), 128>>>(p_mol, p_B, p_atts, p_attd, NM);
    hw_mma_kernel<<<cdiv(NM, 128), 128>>>(p_mol, Wr, p_hW, NM, RR);
    edge_fused_kernel<<<cdiv(NRE * 8, TB), TB>>>(rxn_src, rxn_dst, rxn_rel,
                                                 p_atts, p_attd, p_hW, p_sum, p_molr, NRE, NM);
    norm_elu_kernel<<<cdiv(NM * DD, TB), TB>>>(p_molr, p_sum, NM * DD);

    // ===== reaction readout =====
    fill4_kernel<<<cdiv(NB * 32, TB), TB>>>((float4*)p_feat, NB * 32);
    segsum_kernel<<<cdiv(NM * 16, TB), TB>>>(p_molr, mol2rxn, p_feat, NM, 128, 0);
    segsum_kernel<<<cdiv(NM * 16, TB), TB>>>(p_mol,  mol2rxn, p_feat, NM, 128, 64);

    // ===== MLP head =====
    fc1_kernel<<<dim3(NB / 16, 4), 128>>>(p_feat, w_fc1, b_fc1, prelu, p_hid);
    fc2_kernel<<<dim3(NB / 16, 6), 128>>>(p_hid, w_fc2, b_fc2, out);
}

// round 8
// speedup vs baseline: 4.6920x; 1.3055x over previous
#include <cuda_runtime.h>
#include <cuda_fp16.h>
#include <math.h>
#include <stdint.h>

// ---------------- problem constants ----------------
#define NN      100000
#define NE      800000
#define DD      64
#define RM      8
#define NM      5000
#define NRE     40000
#define RR      4
#define NB      1024
#define DH      512
#define DO      703

// ---------------- scratch ----------------
__device__ __half g_hW [(size_t)RM * NN * DD];   // 102.4 MB fp16
__device__ float g_h1 [(size_t)NN * DD];
__device__ float g_h2 [(size_t)NN * DD];
__device__ float g_atts[(size_t)RM * NN];
__device__ float g_attd[(size_t)RM * NN];
__device__ float g_sum [NM];                     // rxn path only
__device__ int   g_deg   [NN];
__device__ int   g_rowptr[NN + 1];
__device__ int   g_cursor[NN];
__device__ int   g_bsum[128];
__device__ int   g_boff[130];
__device__ uint32_t g_epk[NE];
__device__ float g_mol [(size_t)NM * DD];
__device__ float g_molr[(size_t)NM * DD];
__device__ float g_feat[(size_t)NB * 2 * DD];
__device__ float g_hid [(size_t)NB * DH];

__device__ __forceinline__ void red_add_v4(float* p, float4 v) {
    asm volatile("red.global.add.v4.f32 [%0], {%1,%2,%3,%4};"
                 :: "l"(p), "f"(v.x), "f"(v.y), "f"(v.z), "f"(v.w) : "memory");
}

__global__ void fill_kernel(float* __restrict__ p, float v, int n) {
    int i = blockIdx.x * blockDim.x + threadIdx.x;
    if (i < n) p[i] = v;
}
__global__ void fill4_kernel(float4* __restrict__ p, int n4) {
    int i = blockIdx.x * blockDim.x + threadIdx.x;
    if (i < n4) p[i] = make_float4(0.f, 0.f, 0.f, 0.f);
}
__global__ void filli_kernel(int* __restrict__ p, int v, int n) {
    int i = blockIdx.x * blockDim.x + threadIdx.x;
    if (i < n) p[i] = v;
}

// ================= CSR build =================
__global__ void hist_kernel(const int* __restrict__ dst, int* __restrict__ deg, int E) {
    int e = blockIdx.x * blockDim.x + threadIdx.x;
    if (e < E) atomicAdd(&deg[dst[e]], 1);
}

// per-1024-chunk block sums (256 threads)
__global__ void scan_bsum_kernel(const int* __restrict__ deg, int* __restrict__ bsum, int N) {
    int b = blockIdx.x, t = threadIdx.x;
    int base = b * 1024 + t;
    int s = 0;
    #pragma unroll
    for (int q = 0; q < 4; q++) { int i = base + q * 256; if (i < N) s += deg[i]; }
    #pragma unroll
    for (int o = 16; o; o >>= 1) s += __shfl_xor_sync(0xffffffffu, s, o);
    __shared__ int ws[8];
    if ((t & 31) == 0) ws[t >> 5] = s;
    __syncthreads();
    if (t == 0) { int tot = 0; for (int i = 0; i < 8; i++) tot += ws[i]; bsum[b] = tot; }
}

__global__ void scan_sums_kernel(const int* __restrict__ bsum, int* __restrict__ boff, int nb) {
    if (threadIdx.x == 0) {
        int acc = 0;
        for (int i = 0; i < nb; i++) { boff[i] = acc; acc += bsum[i]; }
        boff[nb] = acc;
    }
}

__global__ void scan_final_kernel(const int* __restrict__ deg, const int* __restrict__ boff,
                                  int* __restrict__ rowptr, int* __restrict__ cursor, int N, int nb) {
    int b = blockIdx.x, t = threadIdx.x, lane = t & 31, wid = t >> 5;
    int idx0 = b * 1024 + t * 4;
    int v0 = 0, v1 = 0, v2 = 0, v3 = 0;
    if (idx0 + 0 < N) v0 = deg[idx0 + 0];
    if (idx0 + 1 < N) v1 = deg[idx0 + 1];
    if (idx0 + 2 < N) v2 = deg[idx0 + 2];
    if (idx0 + 3 < N) v3 = deg[idx0 + 3];
    int tot = v0 + v1 + v2 + v3;
    int inc = tot;
    #pragma unroll
    for (int o = 1; o < 32; o <<= 1) {
        int nv = __shfl_up_sync(0xffffffffu, inc, o);
        if (lane >= o) inc += nv;
    }
    __shared__ int wsum[8], woff[8];
    if (lane == 31) wsum[wid] = inc;
    __syncthreads();
    if (t == 0) { int a = 0; for (int i = 0; i < 8; i++) { woff[i] = a; a += wsum[i]; } }
    __syncthreads();
    int run = boff[b] + woff[wid] + inc - tot;
    if (idx0 + 0 < N) { rowptr[idx0 + 0] = run; cursor[idx0 + 0] = run; } run += v0;
    if (idx0 + 1 < N) { rowptr[idx0 + 1] = run; cursor[idx0 + 1] = run; } run += v1;
    if (idx0 + 2 < N) { rowptr[idx0 + 2] = run; cursor[idx0 + 2] = run; } run += v2;
    if (idx0 + 3 < N) { rowptr[idx0 + 3] = run; cursor[idx0 + 3] = run; }
    if (b == 0 && t == 0) rowptr[N] = boff[nb];
}

__global__ void scatter_kernel(const int* __restrict__ src, const int* __restrict__ dst,
                               const int* __restrict__ rel,
                               int* __restrict__ cursor, uint32_t* __restrict__ epk, int E) {
    int e = blockIdx.x * blockDim.x + threadIdx.x;
    if (e >= E) return;
    int pos = atomicAdd(&cursor[dst[e]], 1);
    epk[pos] = (uint32_t)src[e] | ((uint32_t)rel[e] << 20);
}

// ================= warp-MMA helpers =================
__device__ __forceinline__ uint32_t smem_u32(const void* p) {
    return (uint32_t)__cvta_generic_to_shared(p);
}
#define LDSM_X4(r0, r1, r2, r3, addr) \
    asm volatile("ldmatrix.sync.aligned.m8n8.x4.shared.b16 {%0,%1,%2,%3}, [%4];" \
                 : "=r"(r0), "=r"(r1), "=r"(r2), "=r"(r3) : "r"(addr))
#define LDSM_X2T(r0, r1, addr) \
    asm volatile("ldmatrix.sync.aligned.m8n8.x2.trans.shared.b16 {%0,%1}, [%2];" \
                 : "=r"(r0), "=r"(r1) : "r"(addr))
#define MMA16816(c, a, b) \
    asm volatile("mma.sync.aligned.m16n8k16.row.col.f32.f16.f16.f32 " \
                 "{%0,%1,%2,%3}, {%4,%5,%6,%7}, {%8,%9}, {%0,%1,%2,%3};" \
                 : "+f"((c)[0]), "+f"((c)[1]), "+f"((c)[2]), "+f"((c)[3]) \
                 : "r"((a)[0]), "r"((a)[1]), "r"((a)[2]), "r"((a)[3]), \
                   "r"((b)[0]), "r"((b)[1]))

// ---------------- hW GEMM on HMMA + fused attention-logit epilogue ----------------
// CTA: 128 threads / 4 warps, 128-node tile. A frags held across all R relations.
// Per relation: B frags from W smem tile, 64 MMAs/warp, epilogue computes
// att_s/att_d from accumulator fragments (dot with a_src/a_dst + quad shfl reduce),
// stages fp16 to smem, coalesced STG.128 to hW.
__global__ __launch_bounds__(128)
void hw_mma_kernel(const float* __restrict__ h,
                   const float* __restrict__ W,
                   const float* __restrict__ a_src,
                   const float* __restrict__ a_dst,
                   __half* __restrict__ hW,
                   float* __restrict__ att_s,
                   float* __restrict__ att_d,
                   int N, int R)
{
    __shared__ __align__(16) __half sa [128 * 72];
    __shared__ __align__(16) __half swt[64 * 72];
    __shared__ __align__(16) __half sc [128 * 72];
    __shared__ float sas[8 * 64], sad[8 * 64];

    const int tid  = threadIdx.x;
    const int wid  = tid >> 5;
    const int lane = tid & 31;
    const int n0   = blockIdx.x * 128;

    // attention vectors to smem
    for (int i = tid; i < R * 64; i += 128) { sas[i] = a_src[i]; sad[i] = a_dst[i]; }

    // h tile: fp32 -> fp16, stride 72
    #pragma unroll
    for (int it = 0; it < 8; it++) {
        int chunk = it * 128 + tid;
        int row = chunk >> 3;
        int c8  = (chunk & 7) * 8;
        int n = n0 + row;
        float4 a = make_float4(0.f,0.f,0.f,0.f), b = a;
        if (n < N) {
            a = *(const float4*)&h[(size_t)n * 64 + c8];
            b = *(const float4*)&h[(size_t)n * 64 + c8 + 4];
        }
        __half2 pk[4];
        pk[0] = __floats2half2_rn(a.x, a.y);
        pk[1] = __floats2half2_rn(a.z, a.w);
        pk[2] = __floats2half2_rn(b.x, b.y);
        pk[3] = __floats2half2_rn(b.z, b.w);
        *(uint4*)&sa[row * 72 + c8] = *(uint4*)pk;
    }
    __syncthreads();

    // A fragments, held across relations
    uint32_t afrag[2][4][4];
    {
        const int l15 = lane & 15;
        const int lhi = lane >> 4;
        #pragma unroll
        for (int mt = 0; mt < 2; mt++)
            #pragma unroll
            for (int kk = 0; kk < 4; kk++) {
                uint32_t addr = smem_u32(&sa[(wid * 32 + mt * 16 + l15) * 72 + kk * 16 + lhi * 8]);
                LDSM_X4(afrag[mt][kk][0], afrag[mt][kk][1],
                        afrag[mt][kk][2], afrag[mt][kk][3], addr);
            }
    }

    const int t4 = lane >> 2;
    const int t2 = (lane & 3) * 2;

    for (int r = 0; r < R; r++) {
        __syncthreads();
        // W_r -> smem fp16 [k][c], stride 72
        const float4* Wr4 = (const float4*)(W + (size_t)r * 4096);
        #pragma unroll
        for (int it = 0; it < 8; it++) {
            int i = it * 128 + tid;          // 0..1023 float4
            float4 f = Wr4[i];
            int k = i >> 4, c = (i & 15) * 4;
            *(__half2*)&swt[k * 72 + c]     = __floats2half2_rn(f.x, f.y);
            *(__half2*)&swt[k * 72 + c + 2] = __floats2half2_rn(f.z, f.w);
        }
        __syncthreads();

        float c[2][8][4];
        #pragma unroll
        for (int mt = 0; mt < 2; mt++)
            #pragma unroll
            for (int j = 0; j < 8; j++)
                #pragma unroll
                for (int q = 0; q < 4; q++) c[mt][j][q] = 0.f;

        #pragma unroll
        for (int kk = 0; kk < 4; kk++) {
            uint32_t b[8][2];
            const int l15 = lane & 15;
            #pragma unroll
            for (int j = 0; j < 8; j++) {
                uint32_t addr = smem_u32(&swt[(kk * 16 + l15) * 72 + j * 8]);
                LDSM_X2T(b[j][0], b[j][1], addr);
            }
            #pragma unroll
            for (int mt = 0; mt < 2; mt++)
                #pragma unroll
                for (int j = 0; j < 8; j++)
                    MMA16816(c[mt][j], afrag[mt][kk], b[j]);
        }

        // ---- fused attention logits from fragments ----
        #pragma unroll
        for (int mt = 0; mt < 2; mt++) {
            float ps0 = 0.f, pd0 = 0.f, ps1 = 0.f, pd1 = 0.f;
            #pragma unroll
            for (int j = 0; j < 8; j++) {
                float as0 = sas[r * 64 + j * 8 + t2], as1 = sas[r * 64 + j * 8 + t2 + 1];
                float ad0 = sad[r * 64 + j * 8 + t2], ad1 = sad[r * 64 + j * 8 + t2 + 1];
                ps0 += c[mt][j][0] * as0 + c[mt][j][1] * as1;
                pd0 += c[mt][j][0] * ad0 + c[mt][j][1] * ad1;
                ps1 += c[mt][j][2] * as0 + c[mt][j][3] * as1;
                pd1 += c[mt][j][2] * ad0 + c[mt][j][3] * ad1;
            }
            #pragma unroll
            for (int o = 1; o <= 2; o <<= 1) {
                ps0 += __shfl_xor_sync(0xffffffffu, ps0, o);
                pd0 += __shfl_xor_sync(0xffffffffu, pd0, o);
                ps1 += __shfl_xor_sync(0xffffffffu, ps1, o);
                pd1 += __shfl_xor_sync(0xffffffffu, pd1, o);
            }
            if ((lane & 3) == 0) {
                int n1 = n0 + wid * 32 + mt * 16 + t4;
                int n2 = n1 + 8;
                if (n1 < N) { att_s[(size_t)r * N + n1] = ps0; att_d[(size_t)r * N + n1] = pd0; }
                if (n2 < N) { att_s[(size_t)r * N + n2] = ps1; att_d[(size_t)r * N + n2] = pd1; }
            }
        }

        // ---- stage fp16 + coalesced store ----
        #pragma unroll
        for (int mt = 0; mt < 2; mt++) {
            int rr = wid * 32 + mt * 16 + t4;
            #pragma unroll
            for (int j = 0; j < 8; j++) {
                *(__half2*)&sc[rr * 72 + j * 8 + t2]       = __floats2half2_rn(c[mt][j][0], c[mt][j][1]);
                *(__half2*)&sc[(rr + 8) * 72 + j * 8 + t2] = __floats2half2_rn(c[mt][j][2], c[mt][j][3]);
            }
        }
        __syncthreads();
        #pragma unroll
        for (int it = 0; it < 8; it++) {
            int idx = it * 128 + tid;
            int row = idx >> 3;
            int q   = idx & 7;
            int n = n0 + row;
            if (n < N)
                *(uint4*)&hW[((size_t)r * N + n) * 64 + q * 8] = *(uint4*)&sc[row * 72 + q * 8];
        }
    }
}

// ---------------- CSR edge aggregation: one warp per dst ----------------
__global__ void edge_agg_kernel(const int* __restrict__ rowptr, const uint32_t* __restrict__ epk,
                                const float* __restrict__ att_s, const float* __restrict__ att_d,
                                const __half* __restrict__ hW,
                                float* __restrict__ outh, int N, int R)
{
    int w = (blockIdx.x * blockDim.x + threadIdx.x) >> 5;
    int lane = threadIdx.x & 31;
    if (w >= N) return;
    int beg = rowptr[w], end = rowptr[w + 1];
    float adv = (lane < R) ? att_d[(size_t)lane * N + w] : 0.f;
    float acc0 = 0.f, acc1 = 0.f, ssum = 0.f;
    uint32_t pk = (beg < end) ? epk[beg] : 0u;
    for (int e = beg; e < end; e++) {
        uint32_t pknext = (e + 1 < end) ? epk[e + 1] : 0u;
        int s = pk & 0xFFFFF;
        int r = pk >> 20;
        float sc = att_s[(size_t)r * N + s] + __shfl_sync(0xffffffffu, adv, r);
        sc = (sc > 0.f) ? sc : 0.2f * sc;
        float x = __expf(sc);
        __half2 hv = *(const __half2*)&hW[((size_t)r * N + s) * 64 + lane * 2];
        float2 f = __half22float2(hv);
        acc0 = fmaf(x, f.x, acc0);
        acc1 = fmaf(x, f.y, acc1);
        ssum += x;
        pk = pknext;
    }
    float inv = 1.f / (ssum + 1e-9f);
    float v0 = acc0 * inv, v1 = acc1 * inv;
    v0 = (v0 > 0.f) ? v0 : expm1f(v0);
    v1 = (v1 > 0.f) ? v1 : expm1f(v1);
    *(float2*)&outh[(size_t)w * 64 + lane * 2] = make_float2(v0, v1);
}

// ---------------- atomic edge path (reaction graph only) ----------------
__global__ void edge_fused_kernel(const int* __restrict__ src, const int* __restrict__ dst,
                                  const int* __restrict__ rel,
                                  const float* __restrict__ att_s, const float* __restrict__ att_d,
                                  const __half* __restrict__ hW,
                                  float* __restrict__ dsum, float* __restrict__ agg,
                                  int E, int N)
{
    int t = blockIdx.x * blockDim.x + threadIdx.x;
    int e = t >> 3;
    if (e >= E) return;
    int g = t & 7;
    int s = src[e], d = dst[e], r = rel[e];
    float v = att_s[(size_t)r * N + s] + att_d[(size_t)r * N + d];
    v = (v > 0.f) ? v : 0.2f * v;
    float x = __expf(v);

    uint4 raw = *(const uint4*)&hW[((size_t)r * N + s) * 64 + g * 8];
    __half2* hp = (__half2*)&raw;
    float2 f0 = __half22float2(hp[0]);
    float2 f1 = __half22float2(hp[1]);
    float2 f2 = __half22float2(hp[2]);
    float2 f3 = __half22float2(hp[3]);

    float* base = &agg[(size_t)d * 64 + g * 8];
    red_add_v4(base,     make_float4(x * f0.x, x * f0.y, x * f1.x, x * f1.y));
    red_add_v4(base + 4, make_float4(x * f2.x, x * f2.y, x * f3.x, x * f3.y));
    if (g == 0) atomicAdd(&dsum[d], x);
}

__global__ void norm_elu_kernel(float* __restrict__ agg, const float* __restrict__ dsum, int total) {
    int i = blockIdx.x * blockDim.x + threadIdx.x;
    if (i >= total) return;
    float s = dsum[i >> 6];
    float v = agg[i] / (s + 1e-9f);
    agg[i] = (v > 0.f) ? v : expm1f(v);
}

__global__ void segsum_kernel(const float* __restrict__ x, const int* __restrict__ seg,
                              float* __restrict__ out, int n, int ostride, int ooff)
{
    int t = blockIdx.x * blockDim.x + threadIdx.x;
    int i = t >> 4;
    if (i >= n) return;
    int g = (t & 15) * 4;
    int s = seg[i];
    float4 v = *(const float4*)&x[(size_t)i * 64 + g];
    red_add_v4(&out[(size_t)s * ostride + ooff + g], v);
}

// ---------------- MLP head ----------------
__global__ void fc1_kernel(const float* __restrict__ feat, const float* __restrict__ w,
                           const float* __restrict__ b, const float* __restrict__ prelu,
                           float* __restrict__ out)
{
    const int r0 = blockIdx.x * 16;
    const int c0 = blockIdx.y * 128;
    __shared__ float fs[16][128];
    #pragma unroll
    for (int it = 0; it < 4; it++) {
        int idx4 = it * 128 + threadIdx.x;
        int row = idx4 >> 5, col = (idx4 & 31) * 4;
        *(float4*)&fs[row][col] = *(const float4*)&feat[(size_t)(r0 + row) * 128 + col];
    }
    __syncthreads();
    const int col = c0 + threadIdx.x;
    float acc[16];
    #pragma unroll
    for (int j = 0; j < 16; j++) acc[j] = 0.f;
    #pragma unroll 4
    for (int k = 0; k < 128; k++) {
        float wv = w[k * 512 + col];
        #pragma unroll
        for (int j = 0; j < 16; j++) acc[j] += fs[j][k] * wv;
    }
    float bb = b[col], p = prelu[0];
    #pragma unroll
    for (int j = 0; j < 16; j++) {
        float v = acc[j] + bb;
        out[(size_t)(r0 + j) * 512 + col] = (v > 0.f) ? v : p * v;
    }
}

__global__ void fc2_kernel(const float* __restrict__ hid, const float* __restrict__ w,
                           const float* __restrict__ b, float* __restrict__ out)
{
    const int r0 = blockIdx.x * 16;
    const int c0 = blockIdx.y * 128;
    __shared__ float hs[16][512];
    #pragma unroll
    for (int it = 0; it < 16; it++) {
        int idx4 = it * 128 + threadIdx.x;
        int row = idx4 >> 7, col = (idx4 & 127) * 4;
        *(float4*)&hs[row][col] = *(const float4*)&hid[(size_t)(r0 + row) * 512 + col];
    }
    __syncthreads();
    const int col = c0 + threadIdx.x;
    if (col >= DO) return;
    float acc[16];
    #pragma unroll
    for (int j = 0; j < 16; j++) acc[j] = 0.f;
    #pragma unroll 4
    for (int k = 0; k < 512; k++) {
        float wv = w[k * DO + col];
        #pragma unroll
        for (int j = 0; j < 16; j++) acc[j] += hs[j][k] * wv;
    }
    float bb = b[col];
    #pragma unroll
    for (int j = 0; j < 16; j++)
        out[(size_t)(r0 + j) * DO + col] = acc[j] + bb;
}

// ---------------- launch ----------------
static inline int cdiv(int a, int b) { return (a + b - 1) / b; }

extern "C" void kernel_launch(void* const* d_in, const int* in_sizes, int n_in,
                              void* d_out, int out_size)
{
    const float* node_feats = (const float*)d_in[0];
    const int*   edge_src   = (const int*)  d_in[1];
    const int*   edge_dst   = (const int*)  d_in[2];
    const int*   edge_rel   = (const int*)  d_in[3];
    const int*   node2mol   = (const int*)  d_in[4];
    const int*   rxn_src    = (const int*)  d_in[5];
    const int*   rxn_dst    = (const int*)  d_in[6];
    const int*   rxn_rel    = (const int*)  d_in[7];
    const int*   mol2rxn    = (const int*)  d_in[8];
    const float* W1    = (const float*)d_in[9];
    const float* as1   = (const float*)d_in[10];
    const float* ad1   = (const float*)d_in[11];
    const float* W2    = (const float*)d_in[12];
    const float* as2   = (const float*)d_in[13];
    const float* ad2   = (const float*)d_in[14];
    const float* Wr    = (const float*)d_in[15];
    const float* asr   = (const float*)d_in[16];
    const float* adr   = (const float*)d_in[17];
    const float* w_fc1 = (const float*)d_in[18];
    const float* b_fc1 = (const float*)d_in[19];
    const float* prelu = (const float*)d_in[20];
    const float* w_fc2 = (const float*)d_in[21];
    const float* b_fc2 = (const float*)d_in[22];
    float* out = (float*)d_out;

    __half* p_hW;
    float *p_h1, *p_h2, *p_atts, *p_attd, *p_sum,
          *p_mol, *p_molr, *p_feat, *p_hid;
    int *p_deg, *p_rowptr, *p_cursor, *p_bsum, *p_boff;
    uint32_t* p_epk;
    cudaGetSymbolAddress((void**)&p_hW,    g_hW);
    cudaGetSymbolAddress((void**)&p_h1,    g_h1);
    cudaGetSymbolAddress((void**)&p_h2,    g_h2);
    cudaGetSymbolAddress((void**)&p_atts,  g_atts);
    cudaGetSymbolAddress((void**)&p_attd,  g_attd);
    cudaGetSymbolAddress((void**)&p_sum,   g_sum);
    cudaGetSymbolAddress((void**)&p_deg,   g_deg);
    cudaGetSymbolAddress((void**)&p_rowptr,g_rowptr);
    cudaGetSymbolAddress((void**)&p_cursor,g_cursor);
    cudaGetSymbolAddress((void**)&p_bsum,  g_bsum);
    cudaGetSymbolAddress((void**)&p_boff,  g_boff);
    cudaGetSymbolAddress((void**)&p_epk,   g_epk);
    cudaGetSymbolAddress((void**)&p_mol,   g_mol);
    cudaGetSymbolAddress((void**)&p_molr,  g_molr);
    cudaGetSymbolAddress((void**)&p_feat,  g_feat);
    cudaGetSymbolAddress((void**)&p_hid,   g_hid);

    const int TB = 256;
    const int NBLK = cdiv(NN, 1024);   // 98

    // ===== build atom CSR (reused by both layers) =====
    filli_kernel<<<cdiv(NN, TB), TB>>>(p_deg, 0, NN);
    hist_kernel<<<cdiv(NE, TB), TB>>>(edge_dst, p_deg, NE);
    scan_bsum_kernel<<<NBLK, 256>>>(p_deg, p_bsum, NN);
    scan_sums_kernel<<<1, 32>>>(p_bsum, p_boff, NBLK);
    scan_final_kernel<<<NBLK, 256>>>(p_deg, p_boff, p_rowptr, p_cursor, NN, NBLK);
    scatter_kernel<<<cdiv(NE, TB), TB>>>(edge_src, edge_dst, edge_rel, p_cursor, p_epk, NE);

    // ===== atom layer 1 =====
    hw_mma_kernel<<<cdiv(NN, 128), 128>>>(node_feats, W1, as1, ad1, p_hW, p_atts, p_attd, NN, RM);
    edge_agg_kernel<<<cdiv(NN * 32, TB), TB>>>(p_rowptr, p_epk, p_atts, p_attd, p_hW, p_h1, NN, RM);

    // ===== atom layer 2 =====
    hw_mma_kernel<<<cdiv(NN, 128), 128>>>(p_h1, W2, as2, ad2, p_hW, p_atts, p_attd, NN, RM);
    edge_agg_kernel<<<cdiv(NN * 32, TB), TB>>>(p_rowptr, p_epk, p_atts, p_attd, p_hW, p_h2, NN, RM);

    // ===== molecule readout =====
    fill4_kernel<<<cdiv(NM * 16, TB), TB>>>((float4*)p_mol, NM * 16);
    segsum_kernel<<<cdiv(NN * 16, TB), TB>>>(p_h2, node2mol, p_mol, NN, 64, 0);

    // ===== reaction-level RGAT (atomic path; tiny) =====
    fill_kernel<<<cdiv(NM, TB), TB>>>(p_sum, 0.f, NM);
    fill4_kernel<<<cdiv(NM * 16, TB), TB>>>((float4*)p_molr, NM * 16);
    hw_mma_kernel<<<cdiv(NM, 128), 128>>>(p_mol, Wr, asr, adr, p_hW, p_atts, p_attd, NM, RR);
    edge_fused_kernel<<<cdiv(NRE * 8, TB), TB>>>(rxn_src, rxn_dst, rxn_rel,
                                                 p_atts, p_attd, p_hW, p_sum, p_molr, NRE, NM);
    norm_elu_kernel<<<cdiv(NM * DD, TB), TB>>>(p_molr, p_sum, NM * DD);

    // ===== reaction readout =====
    fill4_kernel<<<cdiv(NB * 32, TB), TB>>>((float4*)p_feat, NB * 32);
    segsum_kernel<<<cdiv(NM * 16, TB), TB>>>(p_molr, mol2rxn, p_feat, NM, 128, 0);
    segsum_kernel<<<cdiv(NM * 16, TB), TB>>>(p_mol,  mol2rxn, p_feat, NM, 128, 64);

    // ===== MLP head =====
    fc1_kernel<<<dim3(NB / 16, 4), 128>>>(p_feat, w_fc1, b_fc1, prelu, p_hid);
    fc2_kernel<<<dim3(NB / 16, 6), 128>>>(p_hid, w_fc2, b_fc2, out);
}

// round 9
// speedup vs baseline: 4.8607x; 1.0360x over previous
#include <cuda_runtime.h>
#include <cuda_fp16.h>
#include <math.h>
#include <stdint.h>

// ---------------- problem constants ----------------
#define NN      100000
#define NE      800000
#define DD      64
#define RM      8
#define NM      5000
#define NRE     40000
#define RR      4
#define NB      1024
#define DH      512
#define DO      703

// ---------------- scratch ----------------
__device__ __half g_hW [(size_t)RM * NN * DD];   // 102.4 MB fp16
__device__ float g_h1 [(size_t)NN * DD];
__device__ float g_atts[(size_t)RM * NN];
__device__ float g_attd[(size_t)RM * NN];
__device__ float g_sum [NM];
__device__ int   g_deg   [NN];
__device__ int   g_rowptr[NN + 1];
__device__ int   g_cursor[NN];
__device__ int   g_bsum[128];
__device__ int   g_boff[130];
__device__ uint32_t g_epk[NE];
__device__ float g_mol [(size_t)NM * DD];
__device__ float g_molr[(size_t)NM * DD];
__device__ float g_feat[(size_t)NB * 2 * DD];
__device__ float g_hid [(size_t)NB * DH];

__device__ __forceinline__ void red_add_v4(float* p, float4 v) {
    asm volatile("red.global.add.v4.f32 [%0], {%1,%2,%3,%4};"
                 :: "l"(p), "f"(v.x), "f"(v.y), "f"(v.z), "f"(v.w) : "memory");
}
__device__ __forceinline__ void red_add_v2(float* p, float2 v) {
    asm volatile("red.global.add.v2.f32 [%0], {%1,%2};"
                 :: "l"(p), "f"(v.x), "f"(v.y) : "memory");
}

__global__ void fill_kernel(float* __restrict__ p, float v, int n) {
    int i = blockIdx.x * blockDim.x + threadIdx.x;
    if (i < n) p[i] = v;
}
__global__ void fill4_kernel(float4* __restrict__ p, int n4) {
    int i = blockIdx.x * blockDim.x + threadIdx.x;
    if (i < n4) p[i] = make_float4(0.f, 0.f, 0.f, 0.f);
}
__global__ void filli_kernel(int* __restrict__ p, int v, int n) {
    int i = blockIdx.x * blockDim.x + threadIdx.x;
    if (i < n) p[i] = v;
}

// ================= CSR build =================
__global__ void hist_kernel(const int* __restrict__ dst, int* __restrict__ deg, int E) {
    int e = blockIdx.x * blockDim.x + threadIdx.x;
    if (e < E) atomicAdd(&deg[dst[e]], 1);
}

__global__ void scan_bsum_kernel(const int* __restrict__ deg, int* __restrict__ bsum, int N) {
    int b = blockIdx.x, t = threadIdx.x;
    int base = b * 1024 + t;
    int s = 0;
    #pragma unroll
    for (int q = 0; q < 4; q++) { int i = base + q * 256; if (i < N) s += deg[i]; }
    #pragma unroll
    for (int o = 16; o; o >>= 1) s += __shfl_xor_sync(0xffffffffu, s, o);
    __shared__ int ws[8];
    if ((t & 31) == 0) ws[t >> 5] = s;
    __syncthreads();
    if (t == 0) { int tot = 0; for (int i = 0; i < 8; i++) tot += ws[i]; bsum[b] = tot; }
}

// parallel exclusive scan over nb (<=128) block sums; one block of 128 threads
__global__ void scan_sums_kernel(const int* __restrict__ bsum, int* __restrict__ boff, int nb) {
    int t = threadIdx.x, lane = t & 31, w = t >> 5;
    int v = (t < nb) ? bsum[t] : 0;
    int inc = v;
    #pragma unroll
    for (int o = 1; o < 32; o <<= 1) {
        int nv = __shfl_up_sync(0xffffffffu, inc, o);
        if (lane >= o) inc += nv;
    }
    __shared__ int ws[4];
    if (lane == 31) ws[w] = inc;
    __syncthreads();
    int add = 0;
    for (int i = 0; i < w; i++) add += ws[i];
    if (t < nb) boff[t] = add + inc - v;
    if (t == 0) boff[nb] = ws[0] + ws[1] + ws[2] + ws[3];
}

__global__ void scan_final_kernel(const int* __restrict__ deg, const int* __restrict__ boff,
                                  int* __restrict__ rowptr, int* __restrict__ cursor, int N, int nb) {
    int b = blockIdx.x, t = threadIdx.x, lane = t & 31, wid = t >> 5;
    int idx0 = b * 1024 + t * 4;
    int v0 = 0, v1 = 0, v2 = 0, v3 = 0;
    if (idx0 + 0 < N) v0 = deg[idx0 + 0];
    if (idx0 + 1 < N) v1 = deg[idx0 + 1];
    if (idx0 + 2 < N) v2 = deg[idx0 + 2];
    if (idx0 + 3 < N) v3 = deg[idx0 + 3];
    int tot = v0 + v1 + v2 + v3;
    int inc = tot;
    #pragma unroll
    for (int o = 1; o < 32; o <<= 1) {
        int nv = __shfl_up_sync(0xffffffffu, inc, o);
        if (lane >= o) inc += nv;
    }
    __shared__ int wsum[8], woff[8];
    if (lane == 31) wsum[wid] = inc;
    __syncthreads();
    if (t == 0) { int a = 0; for (int i = 0; i < 8; i++) { woff[i] = a; a += wsum[i]; } }
    __syncthreads();
    int run = boff[b] + woff[wid] + inc - tot;
    if (idx0 + 0 < N) { rowptr[idx0 + 0] = run; cursor[idx0 + 0] = run; } run += v0;
    if (idx0 + 1 < N) { rowptr[idx0 + 1] = run; cursor[idx0 + 1] = run; } run += v1;
    if (idx0 + 2 < N) { rowptr[idx0 + 2] = run; cursor[idx0 + 2] = run; } run += v2;
    if (idx0 + 3 < N) { rowptr[idx0 + 3] = run; cursor[idx0 + 3] = run; }
    if (b == 0 && t == 0) rowptr[N] = boff[nb];
}

__global__ void scatter_kernel(const int* __restrict__ src, const int* __restrict__ dst,
                               const int* __restrict__ rel,
                               int* __restrict__ cursor, uint32_t* __restrict__ epk, int E) {
    int e = blockIdx.x * blockDim.x + threadIdx.x;
    if (e >= E) return;
    int pos = atomicAdd(&cursor[dst[e]], 1);
    epk[pos] = (uint32_t)src[e] | ((uint32_t)rel[e] << 20);
}

// ================= warp-MMA helpers =================
__device__ __forceinline__ uint32_t smem_u32(const void* p) {
    return (uint32_t)__cvta_generic_to_shared(p);
}
#define LDSM_X4(r0, r1, r2, r3, addr) \
    asm volatile("ldmatrix.sync.aligned.m8n8.x4.shared.b16 {%0,%1,%2,%3}, [%4];" \
                 : "=r"(r0), "=r"(r1), "=r"(r2), "=r"(r3) : "r"(addr))
#define LDSM_X2T(r0, r1, addr) \
    asm volatile("ldmatrix.sync.aligned.m8n8.x2.trans.shared.b16 {%0,%1}, [%2];" \
                 : "=r"(r0), "=r"(r1) : "r"(addr))
#define MMA16816(c, a, b) \
    asm volatile("mma.sync.aligned.m16n8k16.row.col.f32.f16.f16.f32 " \
                 "{%0,%1,%2,%3}, {%4,%5,%6,%7}, {%8,%9}, {%0,%1,%2,%3};" \
                 : "+f"((c)[0]), "+f"((c)[1]), "+f"((c)[2]), "+f"((c)[3]) \
                 : "r"((a)[0]), "r"((a)[1]), "r"((a)[2]), "r"((a)[3]), \
                   "r"((b)[0]), "r"((b)[1]))

// ---------------- hW GEMM on HMMA + fused attention-logit epilogue ----------------
// Double-buffered W tile; warp-private output staging (no block sync in epilogue).
__global__ __launch_bounds__(128)
void hw_mma_kernel(const float* __restrict__ h,
                   const float* __restrict__ W,
                   const float* __restrict__ a_src,
                   const float* __restrict__ a_dst,
                   __half* __restrict__ hW,
                   float* __restrict__ att_s,
                   float* __restrict__ att_d,
                   int N, int R)
{
    __shared__ __align__(16) __half sa [128 * 72];
    __shared__ __align__(16) __half swt[2][64 * 72];
    __shared__ __align__(16) __half sc [128 * 72];
    __shared__ float sas[8 * 64], sad[8 * 64];

    const int tid  = threadIdx.x;
    const int wid  = tid >> 5;
    const int lane = tid & 31;
    const int n0   = blockIdx.x * 128;

    for (int i = tid; i < R * 64; i += 128) { sas[i] = a_src[i]; sad[i] = a_dst[i]; }

    // h tile: fp32 -> fp16, stride 72
    #pragma unroll
    for (int it = 0; it < 8; it++) {
        int chunk = it * 128 + tid;
        int row = chunk >> 3;
        int c8  = (chunk & 7) * 8;
        int n = n0 + row;
        float4 a = make_float4(0.f,0.f,0.f,0.f), b = a;
        if (n < N) {
            a = *(const float4*)&h[(size_t)n * 64 + c8];
            b = *(const float4*)&h[(size_t)n * 64 + c8 + 4];
        }
        __half2 pk[4];
        pk[0] = __floats2half2_rn(a.x, a.y);
        pk[1] = __floats2half2_rn(a.z, a.w);
        pk[2] = __floats2half2_rn(b.x, b.y);
        pk[3] = __floats2half2_rn(b.z, b.w);
        *(uint4*)&sa[row * 72 + c8] = *(uint4*)pk;
    }

    // preload W_0 into swt[0]
    {
        const float4* Wr4 = (const float4*)W;
        #pragma unroll
        for (int it = 0; it < 8; it++) {
            int i = it * 128 + tid;
            float4 f = Wr4[i];
            int k = i >> 4, c = (i & 15) * 4;
            *(__half2*)&swt[0][k * 72 + c]     = __floats2half2_rn(f.x, f.y);
            *(__half2*)&swt[0][k * 72 + c + 2] = __floats2half2_rn(f.z, f.w);
        }
    }
    __syncthreads();

    // A fragments, held across relations
    uint32_t afrag[2][4][4];
    {
        const int l15 = lane & 15;
        const int lhi = lane >> 4;
        #pragma unroll
        for (int mt = 0; mt < 2; mt++)
            #pragma unroll
            for (int kk = 0; kk < 4; kk++) {
                uint32_t addr = smem_u32(&sa[(wid * 32 + mt * 16 + l15) * 72 + kk * 16 + lhi * 8]);
                LDSM_X4(afrag[mt][kk][0], afrag[mt][kk][1],
                        afrag[mt][kk][2], afrag[mt][kk][3], addr);
            }
    }

    const int t4 = lane >> 2;
    const int t2 = (lane & 3) * 2;

    for (int r = 0; r < R; r++) {
        const int buf = r & 1;

        float c[2][8][4];
        #pragma unroll
        for (int mt = 0; mt < 2; mt++)
            #pragma unroll
            for (int j = 0; j < 8; j++)
                #pragma unroll
                for (int q = 0; q < 4; q++) c[mt][j][q] = 0.f;

        #pragma unroll
        for (int kk = 0; kk < 4; kk++) {
            uint32_t b[8][2];
            const int l15 = lane & 15;
            #pragma unroll
            for (int j = 0; j < 8; j++) {
                uint32_t addr = smem_u32(&swt[buf][(kk * 16 + l15) * 72 + j * 8]);
                LDSM_X2T(b[j][0], b[j][1], addr);
            }
            #pragma unroll
            for (int mt = 0; mt < 2; mt++)
                #pragma unroll
                for (int j = 0; j < 8; j++)
                    MMA16816(c[mt][j], afrag[mt][kk], b[j]);
        }

        // convert next relation's W into the other buffer (overlaps epilogue)
        if (r + 1 < R) {
            const float4* Wr4 = (const float4*)(W + (size_t)(r + 1) * 4096);
            #pragma unroll
            for (int it = 0; it < 8; it++) {
                int i = it * 128 + tid;
                float4 f = Wr4[i];
                int k = i >> 4, cc = (i & 15) * 4;
                *(__half2*)&swt[1 - buf][k * 72 + cc]     = __floats2half2_rn(f.x, f.y);
                *(__half2*)&swt[1 - buf][k * 72 + cc + 2] = __floats2half2_rn(f.z, f.w);
            }
        }

        // ---- fused attention logits ----
        #pragma unroll
        for (int mt = 0; mt < 2; mt++) {
            float ps0 = 0.f, pd0 = 0.f, ps1 = 0.f, pd1 = 0.f;
            #pragma unroll
            for (int j = 0; j < 8; j++) {
                float as0 = sas[r * 64 + j * 8 + t2], as1 = sas[r * 64 + j * 8 + t2 + 1];
                float ad0 = sad[r * 64 + j * 8 + t2], ad1 = sad[r * 64 + j * 8 + t2 + 1];
                ps0 += c[mt][j][0] * as0 + c[mt][j][1] * as1;
                pd0 += c[mt][j][0] * ad0 + c[mt][j][1] * ad1;
                ps1 += c[mt][j][2] * as0 + c[mt][j][3] * as1;
                pd1 += c[mt][j][2] * ad0 + c[mt][j][3] * ad1;
            }
            #pragma unroll
            for (int o = 1; o <= 2; o <<= 1) {
                ps0 += __shfl_xor_sync(0xffffffffu, ps0, o);
                pd0 += __shfl_xor_sync(0xffffffffu, pd0, o);
                ps1 += __shfl_xor_sync(0xffffffffu, ps1, o);
                pd1 += __shfl_xor_sync(0xffffffffu, pd1, o);
            }
            if ((lane & 3) == 0) {
                int n1 = n0 + wid * 32 + mt * 16 + t4;
                int n2 = n1 + 8;
                if (n1 < N) { att_s[(size_t)r * N + n1] = ps0; att_d[(size_t)r * N + n1] = pd0; }
                if (n2 < N) { att_s[(size_t)r * N + n2] = ps1; att_d[(size_t)r * N + n2] = pd1; }
            }
        }

        // ---- warp-private staging + coalesced store of own 32 rows ----
        #pragma unroll
        for (int mt = 0; mt < 2; mt++) {
            int rr = wid * 32 + mt * 16 + t4;
            #pragma unroll
            for (int j = 0; j < 8; j++) {
                *(__half2*)&sc[rr * 72 + j * 8 + t2]       = __floats2half2_rn(c[mt][j][0], c[mt][j][1]);
                *(__half2*)&sc[(rr + 8) * 72 + j * 8 + t2] = __floats2half2_rn(c[mt][j][2], c[mt][j][3]);
            }
        }
        __syncwarp();
        #pragma unroll
        for (int it = 0; it < 8; it++) {
            int idx = it * 32 + lane;           // 256 uint4 per warp
            int rowl = idx >> 3;
            int q    = idx & 7;
            int row  = wid * 32 + rowl;
            int n = n0 + row;
            if (n < N)
                *(uint4*)&hW[((size_t)r * N + n) * 64 + q * 8] = *(uint4*)&sc[row * 72 + q * 8];
        }
        __syncthreads();   // next W buffer ready; sc rows reusable
    }
}

// ---------------- CSR edge aggregation: one warp per dst, 2-edge unroll ----------------
template<bool SEG>
__global__ void edge_agg_kernel(const int* __restrict__ rowptr, const uint32_t* __restrict__ epk,
                                const float* __restrict__ att_s, const float* __restrict__ att_d,
                                const __half* __restrict__ hW, const int* __restrict__ seg,
                                float* __restrict__ outh, int N, int R)
{
    int w = (blockIdx.x * blockDim.x + threadIdx.x) >> 5;
    int lane = threadIdx.x & 31;
    if (w >= N) return;
    int beg = rowptr[w], end = rowptr[w + 1];
    float adv = (lane < R) ? att_d[(size_t)lane * N + w] : 0.f;
    float acc0 = 0.f, acc1 = 0.f, ssum = 0.f;
    int e = beg;
    for (; e + 1 < end; e += 2) {
        uint32_t p0 = epk[e], p1 = epk[e + 1];
        int s0 = p0 & 0xFFFFF, r0 = p0 >> 20;
        int s1 = p1 & 0xFFFFF, r1 = p1 >> 20;
        float sc0 = att_s[(size_t)r0 * N + s0] + __shfl_sync(0xffffffffu, adv, r0);
        float sc1 = att_s[(size_t)r1 * N + s1] + __shfl_sync(0xffffffffu, adv, r1);
        sc0 = (sc0 > 0.f) ? sc0 : 0.2f * sc0;
        sc1 = (sc1 > 0.f) ? sc1 : 0.2f * sc1;
        float x0 = __expf(sc0), x1 = __expf(sc1);
        __half2 h0 = *(const __half2*)&hW[((size_t)r0 * N + s0) * 64 + lane * 2];
        __half2 h1 = *(const __half2*)&hW[((size_t)r1 * N + s1) * 64 + lane * 2];
        float2 f0 = __half22float2(h0), f1 = __half22float2(h1);
        acc0 = fmaf(x0, f0.x, acc0); acc1 = fmaf(x0, f0.y, acc1);
        acc0 = fmaf(x1, f1.x, acc0); acc1 = fmaf(x1, f1.y, acc1);
        ssum += x0 + x1;
    }
    if (e < end) {
        uint32_t p0 = epk[e];
        int s0 = p0 & 0xFFFFF, r0 = p0 >> 20;
        float sc0 = att_s[(size_t)r0 * N + s0] + __shfl_sync(0xffffffffu, adv, r0);
        sc0 = (sc0 > 0.f) ? sc0 : 0.2f * sc0;
        float x0 = __expf(sc0);
        __half2 h0 = *(const __half2*)&hW[((size_t)r0 * N + s0) * 64 + lane * 2];
        float2 f0 = __half22float2(h0);
        acc0 = fmaf(x0, f0.x, acc0); acc1 = fmaf(x0, f0.y, acc1);
        ssum += x0;
    }
    float inv = 1.f / (ssum + 1e-9f);
    float v0 = acc0 * inv, v1 = acc1 * inv;
    v0 = (v0 > 0.f) ? v0 : expm1f(v0);
    v1 = (v1 > 0.f) ? v1 : expm1f(v1);
    if (SEG) {
        red_add_v2(&outh[(size_t)seg[w] * 64 + lane * 2], make_float2(v0, v1));
    } else {
        *(float2*)&outh[(size_t)w * 64 + lane * 2] = make_float2(v0, v1);
    }
}

// ---------------- atomic edge path (reaction graph only) ----------------
__global__ void edge_fused_kernel(const int* __restrict__ src, const int* __restrict__ dst,
                                  const int* __restrict__ rel,
                                  const float* __restrict__ att_s, const float* __restrict__ att_d,
                                  const __half* __restrict__ hW,
                                  float* __restrict__ dsum, float* __restrict__ agg,
                                  int E, int N)
{
    int t = blockIdx.x * blockDim.x + threadIdx.x;
    int e = t >> 3;
    if (e >= E) return;
    int g = t & 7;
    int s = src[e], d = dst[e], r = rel[e];
    float v = att_s[(size_t)r * N + s] + att_d[(size_t)r * N + d];
    v = (v > 0.f) ? v : 0.2f * v;
    float x = __expf(v);

    uint4 raw = *(const uint4*)&hW[((size_t)r * N + s) * 64 + g * 8];
    __half2* hp = (__half2*)&raw;
    float2 f0 = __half22float2(hp[0]);
    float2 f1 = __half22float2(hp[1]);
    float2 f2 = __half22float2(hp[2]);
    float2 f3 = __half22float2(hp[3]);

    float* base = &agg[(size_t)d * 64 + g * 8];
    red_add_v4(base,     make_float4(x * f0.x, x * f0.y, x * f1.x, x * f1.y));
    red_add_v4(base + 4, make_float4(x * f2.x, x * f2.y, x * f3.x, x * f3.y));
    if (g == 0) atomicAdd(&dsum[d], x);
}

// normalize+ELU molr and segment-add into feat[:, 0:64]
__global__ void norm_elu_seg_kernel(const float* __restrict__ agg, const float* __restrict__ dsum,
                                    const int* __restrict__ seg, float* __restrict__ feat, int n)
{
    int t = blockIdx.x * blockDim.x + threadIdx.x;   // n*32 threads
    int i = t >> 5;
    if (i >= n) return;
    int g = (t & 31) * 2;
    float s = dsum[i];
    float inv = 1.f / (s + 1e-9f);
    float2 v = *(const float2*)&agg[(size_t)i * 64 + g];
    v.x *= inv; v.y *= inv;
    v.x = (v.x > 0.f) ? v.x : expm1f(v.x);
    v.y = (v.y > 0.f) ? v.y : expm1f(v.y);
    red_add_v2(&feat[(size_t)seg[i] * 128 + g], v);
}

__global__ void segsum_kernel(const float* __restrict__ x, const int* __restrict__ seg,
                              float* __restrict__ out, int n, int ostride, int ooff)
{
    int t = blockIdx.x * blockDim.x + threadIdx.x;
    int i = t >> 4;
    if (i >= n) return;
    int g = (t & 15) * 4;
    int s = seg[i];
    float4 v = *(const float4*)&x[(size_t)i * 64 + g];
    red_add_v4(&out[(size_t)s * ostride + ooff + g], v);
}

// ---------------- MLP head ----------------
__global__ void fc1_kernel(const float* __restrict__ feat, const float* __restrict__ w,
                           const float* __restrict__ b, const float* __restrict__ prelu,
                           float* __restrict__ out)
{
    const int r0 = blockIdx.x * 16;
    const int c0 = blockIdx.y * 128;
    __shared__ float fs[16][128];
    #pragma unroll
    for (int it = 0; it < 4; it++) {
        int idx4 = it * 128 + threadIdx.x;
        int row = idx4 >> 5, col = (idx4 & 31) * 4;
        *(float4*)&fs[row][col] = *(const float4*)&feat[(size_t)(r0 + row) * 128 + col];
    }
    __syncthreads();
    const int col = c0 + threadIdx.x;
    float acc[16];
    #pragma unroll
    for (int j = 0; j < 16; j++) acc[j] = 0.f;
    #pragma unroll 4
    for (int k = 0; k < 128; k++) {
        float wv = w[k * 512 + col];
        #pragma unroll
        for (int j = 0; j < 16; j++) acc[j] += fs[j][k] * wv;
    }
    float bb = b[col], p = prelu[0];
    #pragma unroll
    for (int j = 0; j < 16; j++) {
        float v = acc[j] + bb;
        out[(size_t)(r0 + j) * 512 + col] = (v > 0.f) ? v : p * v;
    }
}

__global__ void fc2_kernel(const float* __restrict__ hid, const float* __restrict__ w,
                           const float* __restrict__ b, float* __restrict__ out)
{
    const int r0 = blockIdx.x * 16;
    const int c0 = blockIdx.y * 128;
    __shared__ float hs[16][512];
    #pragma unroll
    for (int it = 0; it < 16; it++) {
        int idx4 = it * 128 + threadIdx.x;
        int row = idx4 >> 7, col = (idx4 & 127) * 4;
        *(float4*)&hs[row][col] = *(const float4*)&hid[(size_t)(r0 + row) * 512 + col];
    }
    __syncthreads();
    const int col = c0 + threadIdx.x;
    if (col >= DO) return;
    float acc[16];
    #pragma unroll
    for (int j = 0; j < 16; j++) acc[j] = 0.f;
    #pragma unroll 4
    for (int k = 0; k < 512; k++) {
        float wv = w[k * DO + col];
        #pragma unroll
        for (int j = 0; j < 16; j++) acc[j] += hs[j][k] * wv;
    }
    float bb = b[col];
    #pragma unroll
    for (int j = 0; j < 16; j++)
        out[(size_t)(r0 + j) * DO + col] = acc[j] + bb;
}

// ---------------- launch ----------------
static inline int cdiv(int a, int b) { return (a + b - 1) / b; }

extern "C" void kernel_launch(void* const* d_in, const int* in_sizes, int n_in,
                              void* d_out, int out_size)
{
    const float* node_feats = (const float*)d_in[0];
    const int*   edge_src   = (const int*)  d_in[1];
    const int*   edge_dst   = (const int*)  d_in[2];
    const int*   edge_rel   = (const int*)  d_in[3];
    const int*   node2mol   = (const int*)  d_in[4];
    const int*   rxn_src    = (const int*)  d_in[5];
    const int*   rxn_dst    = (const int*)  d_in[6];
    const int*   rxn_rel    = (const int*)  d_in[7];
    const int*   mol2rxn    = (const int*)  d_in[8];
    const float* W1    = (const float*)d_in[9];
    const float* as1   = (const float*)d_in[10];
    const float* ad1   = (const float*)d_in[11];
    const float* W2    = (const float*)d_in[12];
    const float* as2   = (const float*)d_in[13];
    const float* ad2   = (const float*)d_in[14];
    const float* Wr    = (const float*)d_in[15];
    const float* asr   = (const float*)d_in[16];
    const float* adr   = (const float*)d_in[17];
    const float* w_fc1 = (const float*)d_in[18];
    const float* b_fc1 = (const float*)d_in[19];
    const float* prelu = (const float*)d_in[20];
    const float* w_fc2 = (const float*)d_in[21];
    const float* b_fc2 = (const float*)d_in[22];
    float* out = (float*)d_out;

    __half* p_hW;
    float *p_h1, *p_atts, *p_attd, *p_sum, *p_mol, *p_molr, *p_feat, *p_hid;
    int *p_deg, *p_rowptr, *p_cursor, *p_bsum, *p_boff;
    uint32_t* p_epk;
    cudaGetSymbolAddress((void**)&p_hW,    g_hW);
    cudaGetSymbolAddress((void**)&p_h1,    g_h1);
    cudaGetSymbolAddress((void**)&p_atts,  g_atts);
    cudaGetSymbolAddress((void**)&p_attd,  g_attd);
    cudaGetSymbolAddress((void**)&p_sum,   g_sum);
    cudaGetSymbolAddress((void**)&p_deg,   g_deg);
    cudaGetSymbolAddress((void**)&p_rowptr,g_rowptr);
    cudaGetSymbolAddress((void**)&p_cursor,g_cursor);
    cudaGetSymbolAddress((void**)&p_bsum,  g_bsum);
    cudaGetSymbolAddress((void**)&p_boff,  g_boff);
    cudaGetSymbolAddress((void**)&p_epk,   g_epk);
    cudaGetSymbolAddress((void**)&p_mol,   g_mol);
    cudaGetSymbolAddress((void**)&p_molr,  g_molr);
    cudaGetSymbolAddress((void**)&p_feat,  g_feat);
    cudaGetSymbolAddress((void**)&p_hid,   g_hid);

    const int TB = 256;
    const int NBLK = cdiv(NN, 1024);   // 98

    // ===== build atom CSR =====
    filli_kernel<<<cdiv(NN, TB), TB>>>(p_deg, 0, NN);
    hist_kernel<<<cdiv(NE, TB), TB>>>(edge_dst, p_deg, NE);
    scan_bsum_kernel<<<NBLK, 256>>>(p_deg, p_bsum, NN);
    scan_sums_kernel<<<1, 128>>>(p_bsum, p_boff, NBLK);
    scan_final_kernel<<<NBLK, 256>>>(p_deg, p_boff, p_rowptr, p_cursor, NN, NBLK);
    scatter_kernel<<<cdiv(NE, TB), TB>>>(edge_src, edge_dst, edge_rel, p_cursor, p_epk, NE);

    // ===== atom layer 1 =====
    hw_mma_kernel<<<cdiv(NN, 128), 128>>>(node_feats, W1, as1, ad1, p_hW, p_atts, p_attd, NN, RM);
    edge_agg_kernel<false><<<cdiv(NN * 32, TB), TB>>>(p_rowptr, p_epk, p_atts, p_attd, p_hW,
                                                      (const int*)0, p_h1, NN, RM);

    // ===== atom layer 2 (reduces straight into mol) =====
    fill4_kernel<<<cdiv(NM * 16, TB), TB>>>((float4*)p_mol, NM * 16);
    hw_mma_kernel<<<cdiv(NN, 128), 128>>>(p_h1, W2, as2, ad2, p_hW, p_atts, p_attd, NN, RM);
    edge_agg_kernel<true><<<cdiv(NN * 32, TB), TB>>>(p_rowptr, p_epk, p_atts, p_attd, p_hW,
                                                     node2mol, p_mol, NN, RM);

    // ===== reaction-level RGAT =====
    fill_kernel<<<cdiv(NM, TB), TB>>>(p_sum, 0.f, NM);
    fill4_kernel<<<cdiv(NM * 16, TB), TB>>>((float4*)p_molr, NM * 16);
    fill4_kernel<<<cdiv(NB * 32, TB), TB>>>((float4*)p_feat, NB * 32);
    hw_mma_kernel<<<cdiv(NM, 128), 128>>>(p_mol, Wr, asr, adr, p_hW, p_atts, p_attd, NM, RR);
    edge_fused_kernel<<<cdiv(NRE * 8, TB), TB>>>(rxn_src, rxn_dst, rxn_rel,
                                                 p_atts, p_attd, p_hW, p_sum, p_molr, NRE, NM);
    norm_elu_seg_kernel<<<cdiv(NM * 32, TB), TB>>>(p_molr, p_sum, mol2rxn, p_feat, NM);

    // ===== reaction readout (second half: direct mol sums) =====
    segsum_kernel<<<cdiv(NM * 16, TB), TB>>>(p_mol, mol2rxn, p_feat, NM, 128, 64);

    // ===== MLP head =====
    fc1_kernel<<<dim3(NB / 16, 4), 128>>>(p_feat, w_fc1, b_fc1, prelu, p_hid);
    fc2_kernel<<<dim3(NB / 16, 6), 128>>>(p_hid, w_fc2, b_fc2, out);
}